// round 7
// baseline (speedup 1.0000x reference)
#include <cuda_runtime.h>
#include <cuda_bf16.h>
#include <mma.h>
#include <math.h>
#include <stdint.h>

using namespace nvcuda;

// ---------------------------------------------------------------------------
// Problem constants (fixed shapes)
// ---------------------------------------------------------------------------
namespace {
constexpr int NBATCH = 4;
constexpr int L      = 1024;
constexpr int H      = 16;
constexpr int DH     = 64;
constexpr int D      = 1024;   // H * DH
constexpr int DFF    = 4096;
constexpr int NHB    = NBATCH * H;   // 64 attention batches
constexpr int MROWS  = NBATCH * L;   // 4096 token rows
constexpr int LPAD   = 24;           // smem row pitch (bf16 elems), 48B = 16B-multiple
}

// ---------------------------------------------------------------------------
// Scratch (static device globals — no allocation in kernel_launch)
// ---------------------------------------------------------------------------
__device__ float g_q   [NBATCH * L * D];
__device__ float g_k   [NBATCH * L * D];
__device__ float g_v   [NBATCH * L * D];
__device__ float g_attn[NBATCH * L * D];
__device__ float g_y1  [NBATCH * L * D];
__device__ float g_y2  [NBATCH * L * D];
__device__ float g_h   [NBATCH * L * DFF];
__device__ float g_s   [(size_t)NHB * L * L];   // 256 MB score/prob matrix
__device__ float g_padf[NBATCH * L];            // padding mask as float 0/1
__device__ float g_invscale[NBATCH];            // 1/sqrt(valid_len)

// bf16 split-precision operand buffers
__device__ __nv_bfloat16 g_ahi[(size_t)MROWS * DFF];
__device__ __nv_bfloat16 g_alo[(size_t)MROWS * DFF];
__device__ __nv_bfloat16 g_bhi[(size_t)DFF * D];
__device__ __nv_bfloat16 g_blo[(size_t)DFF * D];

// ---------------------------------------------------------------------------
// fp32 -> (bf16 hi, bf16 lo) split conversion, vectorized by 4
// ---------------------------------------------------------------------------
__device__ __forceinline__ void split1(float x, __nv_bfloat16& h, __nv_bfloat16& l)
{
    h = __float2bfloat16_rn(x);
    l = __float2bfloat16_rn(x - __bfloat162float(h));
}

__global__ void __launch_bounds__(256)
f32_to_bf16hl(const float* __restrict__ x, __nv_bfloat16* __restrict__ hi,
              __nv_bfloat16* __restrict__ lo, int n4)
{
    int i = blockIdx.x * blockDim.x + threadIdx.x;
    if (i >= n4) return;
    float4 v = ((const float4*)x)[i];
    __nv_bfloat16 h0, h1, h2, h3, l0, l1, l2, l3;
    split1(v.x, h0, l0); split1(v.y, h1, l1);
    split1(v.z, h2, l2); split1(v.w, h3, l3);
    __nv_bfloat162* hp = (__nv_bfloat162*)hi;
    __nv_bfloat162* lp = (__nv_bfloat162*)lo;
    hp[2*i]   = __nv_bfloat162(h0, h1);
    hp[2*i+1] = __nv_bfloat162(h2, h3);
    lp[2*i]   = __nv_bfloat162(l0, l1);
    lp[2*i+1] = __nv_bfloat162(l2, l3);
}

// Variant with fused bias + ReLU (for FFN1 output -> FFN2 input). ncols4 = row len / 4.
__global__ void __launch_bounds__(256)
f32_to_bf16hl_br(const float* __restrict__ x, const float* __restrict__ bias,
                 __nv_bfloat16* __restrict__ hi, __nv_bfloat16* __restrict__ lo,
                 int n4, int ncols4)
{
    int i = blockIdx.x * blockDim.x + threadIdx.x;
    if (i >= n4) return;
    float4 v = ((const float4*)x)[i];
    const float4 bb = ((const float4*)bias)[i % ncols4];
    v.x = fmaxf(v.x + bb.x, 0.f); v.y = fmaxf(v.y + bb.y, 0.f);
    v.z = fmaxf(v.z + bb.z, 0.f); v.w = fmaxf(v.w + bb.w, 0.f);
    __nv_bfloat16 h0, h1, h2, h3, l0, l1, l2, l3;
    split1(v.x, h0, l0); split1(v.y, h1, l1);
    split1(v.z, h2, l2); split1(v.w, h3, l3);
    __nv_bfloat162* hp = (__nv_bfloat162*)hi;
    __nv_bfloat162* lp = (__nv_bfloat162*)lo;
    hp[2*i]   = __nv_bfloat162(h0, h1);
    hp[2*i+1] = __nv_bfloat162(h2, h3);
    lp[2*i]   = __nv_bfloat162(l0, l1);
    lp[2*i+1] = __nv_bfloat162(l2, l3);
}

// ---------------------------------------------------------------------------
// wmma bf16 split-precision GEMM (NT): C[M,Nn] = A[M,K] * B[Nn,K]^T
// A,B as bf16 hi/lo pairs (row-major, K contiguous).
// C = Ahi*Bhi + Ahi*Blo + Alo*Bhi, fp32 accumulate.
// CTA tile 128x128, 8 warps (2x4), warp tile 64x32, K-chunk 16.
// Requires M%128==0, Nn%128==0, K%16==0.
// ---------------------------------------------------------------------------
__global__ void __launch_bounds__(256)
wmma_gemm(const __nv_bfloat16* __restrict__ Ahi, const __nv_bfloat16* __restrict__ Alo,
          const __nv_bfloat16* __restrict__ Bhi, const __nv_bfloat16* __restrict__ Blo,
          float* __restrict__ C, int M, int Nn, int K)
{
    __shared__ __align__(32) __nv_bfloat16 sAh[128][LPAD];
    __shared__ __align__(32) __nv_bfloat16 sAl[128][LPAD];
    __shared__ __align__(32) __nv_bfloat16 sBh[128][LPAD];
    __shared__ __align__(32) __nv_bfloat16 sBl[128][LPAD];

    const int t   = threadIdx.x;
    const int wid = t >> 5;
    const int wm  = (wid & 1) * 64;   // warp row origin within CTA tile
    const int wn  = (wid >> 1) * 32;  // warp col origin within CTA tile
    const int bm  = blockIdx.y << 7;
    const int bn  = blockIdx.x << 7;

    const int lr = t >> 1;            // 0..127 : tile row loaded by this thread
    const int lk = (t & 1) << 3;      // 0 or 8 : k offset (8 bf16 = 16B)

    wmma::fragment<wmma::accumulator, 16, 16, 16, float> acc[4][2];
#pragma unroll
    for (int i = 0; i < 4; ++i)
#pragma unroll
        for (int j = 0; j < 2; ++j) wmma::fill_fragment(acc[i][j], 0.0f);

    const __nv_bfloat16* gAh = Ahi + (size_t)(bm + lr) * K + lk;
    const __nv_bfloat16* gAl = Alo + (size_t)(bm + lr) * K + lk;
    const __nv_bfloat16* gBh = Bhi + (size_t)(bn + lr) * K + lk;
    const __nv_bfloat16* gBl = Blo + (size_t)(bn + lr) * K + lk;

    // Prologue: prefetch k-chunk 0 into registers.
    uint4 rah = *(const uint4*)gAh;
    uint4 ral = *(const uint4*)gAl;
    uint4 rbh = *(const uint4*)gBh;
    uint4 rbl = *(const uint4*)gBl;

    for (int k0 = 0; k0 < K; k0 += 16) {
        *(uint4*)&sAh[lr][lk] = rah;
        *(uint4*)&sAl[lr][lk] = ral;
        *(uint4*)&sBh[lr][lk] = rbh;
        *(uint4*)&sBl[lr][lk] = rbl;
        __syncthreads();

        if (k0 + 16 < K) {
            gAh += 16; gAl += 16; gBh += 16; gBl += 16;
            rah = *(const uint4*)gAh;
            ral = *(const uint4*)gAl;
            rbh = *(const uint4*)gBh;
            rbl = *(const uint4*)gBl;
        }

#pragma unroll
        for (int i = 0; i < 4; ++i) {
            wmma::fragment<wmma::matrix_a, 16, 16, 16, __nv_bfloat16, wmma::row_major> ah, al;
            wmma::load_matrix_sync(ah, &sAh[wm + 16 * i][0], LPAD);
            wmma::load_matrix_sync(al, &sAl[wm + 16 * i][0], LPAD);
#pragma unroll
            for (int j = 0; j < 2; ++j) {
                wmma::fragment<wmma::matrix_b, 16, 16, 16, __nv_bfloat16, wmma::col_major> bh, bl;
                wmma::load_matrix_sync(bh, &sBh[wn + 16 * j][0], LPAD);
                wmma::load_matrix_sync(bl, &sBl[wn + 16 * j][0], LPAD);
                wmma::mma_sync(acc[i][j], ah, bh, acc[i][j]);
                wmma::mma_sync(acc[i][j], ah, bl, acc[i][j]);
                wmma::mma_sync(acc[i][j], al, bh, acc[i][j]);
            }
        }
        __syncthreads();
    }

#pragma unroll
    for (int i = 0; i < 4; ++i)
#pragma unroll
        for (int j = 0; j < 2; ++j)
            wmma::store_matrix_sync(
                C + (size_t)(bm + wm + 16 * i) * Nn + bn + wn + 16 * j,
                acc[i][j], Nn, wmma::mem_row_major);
}

// ---------------------------------------------------------------------------
// Padding-mask decode + per-sample scaling (bool width sniffed from causal mask)
// ---------------------------------------------------------------------------
__global__ void pad_prep_kernel(const unsigned char* __restrict__ maskb,
                                const unsigned char* __restrict__ padb)
{
    __shared__ int s_cnt[NBATCH];
    __shared__ int s_mode;
    const int t = threadIdx.x;
    if (t < NBATCH) s_cnt[t] = 0;
    if (t == 0) {
        int mode = 2;                 // default: f32
        if (maskb[1] == 1)      mode = 0;   // u8
        else if (maskb[4] == 1) mode = 1;   // i32
        s_mode = mode;
    }
    __syncthreads();
    const int mode = s_mode;
    for (int i = t; i < NBATCH * L; i += blockDim.x) {
        int v;
        if (mode == 0)      v = (padb[i] != 0);
        else if (mode == 1) v = (((const int*)padb)[i] != 0);
        else                v = (((const float*)padb)[i] != 0.0f);
        g_padf[i] = (float)v;
        if (v) atomicAdd(&s_cnt[i / L], 1);
    }
    __syncthreads();
    if (t < NBATCH) g_invscale[t] = rsqrtf((float)(L - s_cnt[t]));
}

// ---------------------------------------------------------------------------
// Attention scores (unchanged from passing baseline)
// ---------------------------------------------------------------------------
template<bool CAUSAL>
__global__ void __launch_bounds__(256)
attn_score(const float* __restrict__ Q, const float* __restrict__ Kin,
           float* __restrict__ S)
{
    const int b  = blockIdx.z;
    const int n  = b / H;
    const int h  = b % H;
    const int br = blockIdx.y << 6;
    const int bc = blockIdx.x << 6;
    const int t  = threadIdx.x;
    const int ty = t >> 4, tx = t & 15;

    float* Sb = S + (size_t)b * L * L;

    if (CAUSAL && bc > br) {
        const float4 m4 = {-1e30f, -1e30f, -1e30f, -1e30f};
#pragma unroll
        for (int i = 0; i < 4; ++i)
            *(float4*)(Sb + (size_t)(br + (ty << 2) + i) * L + bc + (tx << 2)) = m4;
        return;
    }

    const float* Qb = Q   + (size_t)n * L * D + h * DH;
    const float* Kb = Kin + (size_t)n * L * D + h * DH;

    __shared__ float Qs[16][64];
    __shared__ float Ks[16][64];
    const int lr = t >> 2;
    const int lc = (t & 3) << 2;

    float acc[4][4] = {};
#pragma unroll
    for (int k0 = 0; k0 < DH; k0 += 16) {
        float4 qv = *(const float4*)(Qb + (size_t)(br + lr) * D + k0 + lc);
        float4 kv = *(const float4*)(Kb + (size_t)(bc + lr) * D + k0 + lc);
        Qs[lc + 0][lr] = qv.x; Qs[lc + 1][lr] = qv.y;
        Qs[lc + 2][lr] = qv.z; Qs[lc + 3][lr] = qv.w;
        Ks[lc + 0][lr] = kv.x; Ks[lc + 1][lr] = kv.y;
        Ks[lc + 2][lr] = kv.z; Ks[lc + 3][lr] = kv.w;
        __syncthreads();
#pragma unroll
        for (int kk = 0; kk < 16; ++kk) {
            float4 a4 = *(const float4*)&Qs[kk][ty << 2];
            float4 b4 = *(const float4*)&Ks[kk][tx << 2];
            float a[4] = {a4.x, a4.y, a4.z, a4.w};
            float c[4] = {b4.x, b4.y, b4.z, b4.w};
#pragma unroll
            for (int i = 0; i < 4; ++i)
#pragma unroll
                for (int j = 0; j < 4; ++j)
                    acc[i][j] = fmaf(a[i], c[j], acc[i][j]);
        }
        __syncthreads();
    }

    const float inv = g_invscale[n];
#pragma unroll
    for (int i = 0; i < 4; ++i) {
        const int row = br + (ty << 2) + i;
#pragma unroll
        for (int j = 0; j < 4; ++j) {
            const int col = bc + (tx << 2) + j;
            float sc = acc[i][j] * inv;
            if (CAUSAL && col > row) sc = -1e30f;
            if (g_padf[n * L + col] != 0.f) sc = -1e30f;
            acc[i][j] = sc;
        }
        float4 v = {acc[i][0], acc[i][1], acc[i][2], acc[i][3]};
        *(float4*)(Sb + (size_t)row * L + bc + (tx << 2)) = v;
    }
}

// ---------------------------------------------------------------------------
// Row softmax over length L (in-place), one 128-thread block per row.
// ---------------------------------------------------------------------------
__global__ void __launch_bounds__(128)
softmax_rows(float* __restrict__ S)
{
    float* p = S + (size_t)blockIdx.x * L;
    const int t = threadIdx.x;

    float v[8];
#pragma unroll
    for (int i = 0; i < 8; ++i) v[i] = p[t + (i << 7)];

    float m = v[0];
#pragma unroll
    for (int i = 1; i < 8; ++i) m = fmaxf(m, v[i]);

    __shared__ float red[4];
#pragma unroll
    for (int o = 16; o; o >>= 1) m = fmaxf(m, __shfl_xor_sync(0xffffffffu, m, o));
    if ((t & 31) == 0) red[t >> 5] = m;
    __syncthreads();
    m = fmaxf(fmaxf(red[0], red[1]), fmaxf(red[2], red[3]));
    __syncthreads();

    float s = 0.f;
#pragma unroll
    for (int i = 0; i < 8; ++i) { v[i] = __expf(v[i] - m); s += v[i]; }
#pragma unroll
    for (int o = 16; o; o >>= 1) s += __shfl_xor_sync(0xffffffffu, s, o);
    if ((t & 31) == 0) red[t >> 5] = s;
    __syncthreads();
    s = red[0] + red[1] + red[2] + red[3];

    const float invs = 1.f / s;
#pragma unroll
    for (int i = 0; i < 8; ++i) p[t + (i << 7)] = v[i] * invs;
}

// ---------------------------------------------------------------------------
// Attention output: O_b = P_b (L x L) * V_b (L x DH), batched over b.
// ---------------------------------------------------------------------------
__global__ void __launch_bounds__(256)
attn_out(const float* __restrict__ S, const float* __restrict__ V,
         float* __restrict__ O)
{
    const int b  = blockIdx.y;
    const int n  = b / H;
    const int h  = b % H;
    const int br = blockIdx.x << 6;

    const float* Sb = S + (size_t)b * L * L;
    const float* Vb = V + (size_t)n * L * D + h * DH;
    float*       Ob = O + (size_t)n * L * D + h * DH;

    __shared__ float Ps[32][64];
    __shared__ float Vs[32][64];

    const int t  = threadIdx.x;
    const int ty = t >> 4, tx = t & 15;
    const int plr = t >> 2, plc = (t & 3) << 3;
    const int vlr = t >> 3, vlc = (t & 7) << 3;

    float acc[4][4] = {};
    for (int k0 = 0; k0 < L; k0 += 32) {
        float4 p0 = *(const float4*)(Sb + (size_t)(br + plr) * L + k0 + plc);
        float4 p1 = *(const float4*)(Sb + (size_t)(br + plr) * L + k0 + plc + 4);
        Ps[plc + 0][plr] = p0.x; Ps[plc + 1][plr] = p0.y;
        Ps[plc + 2][plr] = p0.z; Ps[plc + 3][plr] = p0.w;
        Ps[plc + 4][plr] = p1.x; Ps[plc + 5][plr] = p1.y;
        Ps[plc + 6][plr] = p1.z; Ps[plc + 7][plr] = p1.w;
        float4 v0 = *(const float4*)(Vb + (size_t)(k0 + vlr) * D + vlc);
        float4 v1 = *(const float4*)(Vb + (size_t)(k0 + vlr) * D + vlc + 4);
        *(float4*)&Vs[vlr][vlc]     = v0;
        *(float4*)&Vs[vlr][vlc + 4] = v1;
        __syncthreads();

#pragma unroll
        for (int kk = 0; kk < 32; ++kk) {
            float4 a4 = *(const float4*)&Ps[kk][ty << 2];
            float4 b4 = *(const float4*)&Vs[kk][tx << 2];
            float a[4] = {a4.x, a4.y, a4.z, a4.w};
            float c[4] = {b4.x, b4.y, b4.z, b4.w};
#pragma unroll
            for (int i = 0; i < 4; ++i)
#pragma unroll
                for (int j = 0; j < 4; ++j)
                    acc[i][j] = fmaf(a[i], c[j], acc[i][j]);
        }
        __syncthreads();
    }

#pragma unroll
    for (int i = 0; i < 4; ++i) {
        float4 v = {acc[i][0], acc[i][1], acc[i][2], acc[i][3]};
        *(float4*)(Ob + (size_t)(br + (ty << 2) + i) * D + (tx << 2)) = v;
    }
}

// ---------------------------------------------------------------------------
// Fused residual add (+optional bias) + LayerNorm
// ---------------------------------------------------------------------------
__device__ __forceinline__ float block_sum_256(float v, float* red)
{
#pragma unroll
    for (int o = 16; o; o >>= 1) v += __shfl_xor_sync(0xffffffffu, v, o);
    const int t = threadIdx.x;
    if ((t & 31) == 0) red[t >> 5] = v;
    __syncthreads();
    float s = red[0];
#pragma unroll
    for (int i = 1; i < 8; ++i) s += red[i];
    __syncthreads();
    return s;
}

__global__ void __launch_bounds__(256)
add_ln(const float* __restrict__ A, const float* __restrict__ R,
       const float* __restrict__ bias,   // optional per-column bias (len D) or null
       const float* __restrict__ gam, const float* __restrict__ bet,
       float* __restrict__ Y)
{
    const int row = blockIdx.x;
    const float* a = A + (size_t)row * D;
    const float* r = R + (size_t)row * D;
    float*       y = Y + (size_t)row * D;

    __shared__ float xs[D];
    __shared__ float red[8];
    const int t = threadIdx.x;

    float lsum = 0.f;
    for (int i = t; i < D; i += 256) {
        float v = a[i] + r[i];
        if (bias) v += bias[i];
        xs[i] = v;
        lsum += v;
    }
    const float mu = block_sum_256(lsum, red) * (1.f / D);

    float lvar = 0.f;
    for (int i = t; i < D; i += 256) {
        const float d = xs[i] - mu;
        lvar += d * d;
    }
    const float var = block_sum_256(lvar, red) * (1.f / D);
    const float sdev = rsqrtf(var + 1e-5f);

    for (int i = t; i < D; i += 256)
        y[i] = (xs[i] - mu) * sdev * gam[i] + bet[i];
}

// ---------------------------------------------------------------------------
// Launch
// ---------------------------------------------------------------------------
extern "C" void kernel_launch(void* const* d_in, const int* in_sizes, int n_in,
                              void* d_out, int out_size)
{
    (void)in_sizes; (void)n_in; (void)out_size;

    const float* encoded = (const float*)d_in[0];
    const float* Yin     = (const float*)d_in[1];
    const unsigned char* maskb = (const unsigned char*)d_in[2];
    const unsigned char* padb  = (const unsigned char*)d_in[3];
    const float* Wq1 = (const float*)d_in[4];
    const float* Wk1 = (const float*)d_in[5];
    const float* Wv1 = (const float*)d_in[6];
    const float* ga1 = (const float*)d_in[7];
    const float* bb1 = (const float*)d_in[8];
    const float* Wq2 = (const float*)d_in[9];
    const float* Wk2 = (const float*)d_in[10];
    const float* Wv2 = (const float*)d_in[11];
    const float* ga2 = (const float*)d_in[12];
    const float* bb2 = (const float*)d_in[13];
    const float* We  = (const float*)d_in[14];
    const float* be  = (const float*)d_in[15];
    const float* Wc  = (const float*)d_in[16];
    const float* bc  = (const float*)d_in[17];
    const float* ga3 = (const float*)d_in[18];
    const float* bb3 = (const float*)d_in[19];
    float* out = (float*)d_out;

    float *pq, *pk, *pv, *pa, *py1, *py2, *ph, *ps;
    __nv_bfloat16 *pahi, *palo, *pbhi, *pblo;
    cudaGetSymbolAddress((void**)&pq,  g_q);
    cudaGetSymbolAddress((void**)&pk,  g_k);
    cudaGetSymbolAddress((void**)&pv,  g_v);
    cudaGetSymbolAddress((void**)&pa,  g_attn);
    cudaGetSymbolAddress((void**)&py1, g_y1);
    cudaGetSymbolAddress((void**)&py2, g_y2);
    cudaGetSymbolAddress((void**)&ph,  g_h);
    cudaGetSymbolAddress((void**)&ps,  g_s);
    cudaGetSymbolAddress((void**)&pahi, g_ahi);
    cudaGetSymbolAddress((void**)&palo, g_alo);
    cudaGetSymbolAddress((void**)&pbhi, g_bhi);
    cudaGetSymbolAddress((void**)&pblo, g_blo);

    pad_prep_kernel<<<1, 256>>>(maskb, padb);

    const dim3 gScore(L / 64, L / 64, NHB);        // (16, 16, 64)
    const dim3 gOut(L / 64, NHB);                  // (16, 64)
    const dim3 gP(D / 128, MROWS / 128);           // projections: (8, 32)
    const dim3 gF1(DFF / 128, MROWS / 128);        // FFN1: (32, 32)
    const dim3 gF2(D / 128, MROWS / 128);          // FFN2: (8, 32)

    auto convA = [&](const float* x, int n) {
        f32_to_bf16hl<<<(n / 4 + 255) / 256, 256>>>(x, pahi, palo, n / 4);
    };
    auto convB = [&](const float* x, int n) {
        f32_to_bf16hl<<<(n / 4 + 255) / 256, 256>>>(x, pbhi, pblo, n / 4);
    };

    // ---- masked self-attention + residual + LN ----
    convA(Yin, MROWS * D);
    convB(Wq1, D * D);
    wmma_gemm<<<gP, 256>>>(pahi, palo, pbhi, pblo, pq, MROWS, D, D);
    convB(Wk1, D * D);
    wmma_gemm<<<gP, 256>>>(pahi, palo, pbhi, pblo, pk, MROWS, D, D);
    convB(Wv1, D * D);
    wmma_gemm<<<gP, 256>>>(pahi, palo, pbhi, pblo, pv, MROWS, D, D);
    attn_score<true><<<gScore, 256>>>(pq, pk, ps);
    softmax_rows<<<NHB * L, 128>>>(ps);
    attn_out<<<gOut, 256>>>(ps, pv, pa);
    add_ln<<<MROWS, 256>>>(pa, Yin, nullptr, ga1, bb1, py1);

    // ---- cross-attention + residual + LN ----
    convA(py1, MROWS * D);
    convB(Wq2, D * D);
    wmma_gemm<<<gP, 256>>>(pahi, palo, pbhi, pblo, pq, MROWS, D, D);
    convA(encoded, MROWS * D);
    convB(Wk2, D * D);
    wmma_gemm<<<gP, 256>>>(pahi, palo, pbhi, pblo, pk, MROWS, D, D);
    convB(Wv2, D * D);
    wmma_gemm<<<gP, 256>>>(pahi, palo, pbhi, pblo, pv, MROWS, D, D);
    attn_score<false><<<gScore, 256>>>(pq, pk, ps);
    softmax_rows<<<NHB * L, 128>>>(ps);
    attn_out<<<gOut, 256>>>(ps, pv, pa);
    add_ln<<<MROWS, 256>>>(pa, py1, nullptr, ga2, bb2, py2);

    // ---- FFN + residual + LN ----
    convA(py2, MROWS * D);
    convB(We, DFF * D);
    wmma_gemm<<<gF1, 256>>>(pahi, palo, pbhi, pblo, ph, MROWS, DFF, D);
    // bias + ReLU fused into the split-conversion of FFN1's output
    f32_to_bf16hl_br<<<(MROWS * DFF / 4 + 255) / 256, 256>>>(ph, be, pahi, palo,
                                                             MROWS * DFF / 4, DFF / 4);
    convB(Wc, D * DFF);
    wmma_gemm<<<gF2, 256>>>(pahi, palo, pbhi, pblo, pa, MROWS, D, DFF);
    // FFN2 bias fused into final add+LN
    add_ln<<<MROWS, 256>>>(pa, py2, bc, ga3, bb3, out);
}

// round 10
// speedup vs baseline: 1.5328x; 1.5328x over previous
#include <cuda_runtime.h>
#include <cuda_bf16.h>
#include <mma.h>
#include <math.h>
#include <stdint.h>

using namespace nvcuda;

// ---------------------------------------------------------------------------
// Problem constants (fixed shapes)
// ---------------------------------------------------------------------------
namespace {
constexpr int NBATCH = 4;
constexpr int L      = 1024;
constexpr int H      = 16;
constexpr int DH     = 64;
constexpr int D      = 1024;   // H * DH
constexpr int DFF    = 4096;
constexpr int NHB    = NBATCH * H;   // 64 attention batches
constexpr int MROWS  = NBATCH * L;   // 4096 token rows

// wmma GEMM tiling
constexpr int BK   = 32;             // K elems per stage
constexpr int BKP  = 40;             // smem row pitch in bf16 elems (80B, 16B-mult)
constexpr int STAGE_ELEMS = 128 * BKP;            // one array, one stage
constexpr int GEMM_SMEM_BYTES = 4 * 2 * STAGE_ELEMS * 2;  // 4 arrays x 2 stages x 2B = 81920
}

// ---------------------------------------------------------------------------
// Scratch (static device globals — no allocation in kernel_launch)
// ---------------------------------------------------------------------------
__device__ float g_q   [NBATCH * L * D];
__device__ float g_k   [NBATCH * L * D];
__device__ float g_v   [NBATCH * L * D];
__device__ float g_attn[NBATCH * L * D];
__device__ float g_y1  [NBATCH * L * D];
__device__ float g_y2  [NBATCH * L * D];
__device__ float g_h   [NBATCH * L * DFF];
__device__ float g_s   [(size_t)NHB * L * L];   // 256 MB score/prob matrix
__device__ float g_padf[NBATCH * L];            // padding mask as float 0/1
__device__ float g_invscale[NBATCH];            // 1/sqrt(valid_len)

// bf16 split-precision operand buffers
__device__ __nv_bfloat16 g_ahi[(size_t)MROWS * DFF];
__device__ __nv_bfloat16 g_alo[(size_t)MROWS * DFF];
__device__ __nv_bfloat16 g_bhi[(size_t)DFF * D];
__device__ __nv_bfloat16 g_blo[(size_t)DFF * D];

// ---------------------------------------------------------------------------
// cp.async helpers
// ---------------------------------------------------------------------------
__device__ __forceinline__ void cp16(void* dst_smem, const void* src_gmem)
{
    uint32_t d = (uint32_t)__cvta_generic_to_shared(dst_smem);
    asm volatile("cp.async.cg.shared.global [%0], [%1], 16;" :: "r"(d), "l"(src_gmem));
}
__device__ __forceinline__ void cp_commit()
{
    asm volatile("cp.async.commit_group;");
}
template<int N>
__device__ __forceinline__ void cp_wait()
{
    asm volatile("cp.async.wait_group %0;" :: "n"(N));
}

// ---------------------------------------------------------------------------
// fp32 -> (bf16 hi, bf16 lo) split conversion, vectorized by 4
// ---------------------------------------------------------------------------
__device__ __forceinline__ void split1(float x, __nv_bfloat16& h, __nv_bfloat16& l)
{
    h = __float2bfloat16_rn(x);
    l = __float2bfloat16_rn(x - __bfloat162float(h));
}

__global__ void __launch_bounds__(256)
f32_to_bf16hl(const float* __restrict__ x, __nv_bfloat16* __restrict__ hi,
              __nv_bfloat16* __restrict__ lo, int n4)
{
    int i = blockIdx.x * blockDim.x + threadIdx.x;
    if (i >= n4) return;
    float4 v = ((const float4*)x)[i];
    __nv_bfloat16 h0, h1, h2, h3, l0, l1, l2, l3;
    split1(v.x, h0, l0); split1(v.y, h1, l1);
    split1(v.z, h2, l2); split1(v.w, h3, l3);
    __nv_bfloat162* hp = (__nv_bfloat162*)hi;
    __nv_bfloat162* lp = (__nv_bfloat162*)lo;
    hp[2*i]   = __nv_bfloat162(h0, h1);
    hp[2*i+1] = __nv_bfloat162(h2, h3);
    lp[2*i]   = __nv_bfloat162(l0, l1);
    lp[2*i+1] = __nv_bfloat162(l2, l3);
}

// Variant with fused bias + ReLU (for FFN1 output -> FFN2 input). ncols4 = row len / 4.
__global__ void __launch_bounds__(256)
f32_to_bf16hl_br(const float* __restrict__ x, const float* __restrict__ bias,
                 __nv_bfloat16* __restrict__ hi, __nv_bfloat16* __restrict__ lo,
                 int n4, int ncols4)
{
    int i = blockIdx.x * blockDim.x + threadIdx.x;
    if (i >= n4) return;
    float4 v = ((const float4*)x)[i];
    const float4 bb = ((const float4*)bias)[i % ncols4];
    v.x = fmaxf(v.x + bb.x, 0.f); v.y = fmaxf(v.y + bb.y, 0.f);
    v.z = fmaxf(v.z + bb.z, 0.f); v.w = fmaxf(v.w + bb.w, 0.f);
    __nv_bfloat16 h0, h1, h2, h3, l0, l1, l2, l3;
    split1(v.x, h0, l0); split1(v.y, h1, l1);
    split1(v.z, h2, l2); split1(v.w, h3, l3);
    __nv_bfloat162* hp = (__nv_bfloat162*)hi;
    __nv_bfloat162* lp = (__nv_bfloat162*)lo;
    hp[2*i]   = __nv_bfloat162(h0, h1);
    hp[2*i+1] = __nv_bfloat162(h2, h3);
    lp[2*i]   = __nv_bfloat162(l0, l1);
    lp[2*i+1] = __nv_bfloat162(l2, l3);
}

// ---------------------------------------------------------------------------
// wmma bf16 split-precision GEMM (NT): C[M,Nn] = A[M,K] * B[Nn,K]^T
// A,B as bf16 hi/lo pairs (row-major, K contiguous).
// C = Ahi*Bhi + Ahi*Blo + Alo*Bhi, fp32 accumulate.
// CTA tile 128x128, 8 warps (2x4), warp tile 64x32.
// cp.async double-buffered smem, BK=32 per stage.
// Requires M%128==0, Nn%128==0, K%32==0.
// ---------------------------------------------------------------------------
__global__ void __launch_bounds__(256)
wmma_gemm(const __nv_bfloat16* __restrict__ Ahi, const __nv_bfloat16* __restrict__ Alo,
          const __nv_bfloat16* __restrict__ Bhi, const __nv_bfloat16* __restrict__ Blo,
          float* __restrict__ C, int M, int Nn, int K)
{
    extern __shared__ __align__(128) __nv_bfloat16 sm[];
    __nv_bfloat16* const sAh = sm;                      // [2][128][BKP]
    __nv_bfloat16* const sAl = sm + 2 * STAGE_ELEMS;
    __nv_bfloat16* const sBh = sm + 4 * STAGE_ELEMS;
    __nv_bfloat16* const sBl = sm + 6 * STAGE_ELEMS;

    const int t   = threadIdx.x;
    const int wid = t >> 5;
    const int wm  = (wid & 1) * 64;   // warp row origin within CTA tile
    const int wn  = (wid >> 1) * 32;  // warp col origin within CTA tile
    const int bm  = blockIdx.y << 7;
    const int bn  = blockIdx.x << 7;

    // Loader mapping: row = t>>1; each thread covers 32B (2x16B) of the 64B row.
    const int lr   = t >> 1;
    const int half = (t & 1) << 4;    // elem offset 0 or 16

    const __nv_bfloat16* gAh = Ahi + (size_t)(bm + lr) * K + half;
    const __nv_bfloat16* gAl = Alo + (size_t)(bm + lr) * K + half;
    const __nv_bfloat16* gBh = Bhi + (size_t)(bn + lr) * K + half;
    const __nv_bfloat16* gBl = Blo + (size_t)(bn + lr) * K + half;
    const int sOff = lr * BKP + half; // elem offset within a stage

    wmma::fragment<wmma::accumulator, 16, 16, 16, float> acc[4][2];
#pragma unroll
    for (int i = 0; i < 4; ++i)
#pragma unroll
        for (int j = 0; j < 2; ++j) wmma::fill_fragment(acc[i][j], 0.0f);

    const int nIter = K >> 5;   // K / 32

    auto issue_stage = [&](int s, int k0) {
        __nv_bfloat16* dAh = sAh + s * STAGE_ELEMS + sOff;
        __nv_bfloat16* dAl = sAl + s * STAGE_ELEMS + sOff;
        __nv_bfloat16* dBh = sBh + s * STAGE_ELEMS + sOff;
        __nv_bfloat16* dBl = sBl + s * STAGE_ELEMS + sOff;
        cp16(dAh,     gAh + k0);
        cp16(dAh + 8, gAh + k0 + 8);
        cp16(dAl,     gAl + k0);
        cp16(dAl + 8, gAl + k0 + 8);
        cp16(dBh,     gBh + k0);
        cp16(dBh + 8, gBh + k0 + 8);
        cp16(dBl,     gBl + k0);
        cp16(dBl + 8, gBl + k0 + 8);
    };

    // Prologue: stage 0 in flight.
    issue_stage(0, 0);
    cp_commit();

    for (int it = 0; it < nIter; ++it) {
        if (it + 1 < nIter) {
            issue_stage((it + 1) & 1, (it + 1) * BK);
            cp_commit();
            cp_wait<1>();     // oldest group (current stage) complete
        } else {
            cp_wait<0>();     // last stage: wait for everything
        }
        __syncthreads();

        const int s = it & 1;
        const __nv_bfloat16* pAh = sAh + s * STAGE_ELEMS;
        const __nv_bfloat16* pAl = sAl + s * STAGE_ELEMS;
        const __nv_bfloat16* pBh = sBh + s * STAGE_ELEMS;
        const __nv_bfloat16* pBl = sBl + s * STAGE_ELEMS;

#pragma unroll
        for (int ks = 0; ks < 2; ++ks) {
            const int kc = ks * 16;
            wmma::fragment<wmma::matrix_b, 16, 16, 16, __nv_bfloat16, wmma::col_major> bh[2], bl[2];
#pragma unroll
            for (int j = 0; j < 2; ++j) {
                wmma::load_matrix_sync(bh[j], pBh + (wn + 16 * j) * BKP + kc, BKP);
                wmma::load_matrix_sync(bl[j], pBl + (wn + 16 * j) * BKP + kc, BKP);
            }
#pragma unroll
            for (int i = 0; i < 4; ++i) {
                wmma::fragment<wmma::matrix_a, 16, 16, 16, __nv_bfloat16, wmma::row_major> ah, al;
                wmma::load_matrix_sync(ah, pAh + (wm + 16 * i) * BKP + kc, BKP);
                wmma::load_matrix_sync(al, pAl + (wm + 16 * i) * BKP + kc, BKP);
#pragma unroll
                for (int j = 0; j < 2; ++j) {
                    wmma::mma_sync(acc[i][j], ah, bh[j], acc[i][j]);
                    wmma::mma_sync(acc[i][j], ah, bl[j], acc[i][j]);
                    wmma::mma_sync(acc[i][j], al, bh[j], acc[i][j]);
                }
            }
        }
        __syncthreads();   // stage fully consumed before it is overwritten
    }

#pragma unroll
    for (int i = 0; i < 4; ++i)
#pragma unroll
        for (int j = 0; j < 2; ++j)
            wmma::store_matrix_sync(
                C + (size_t)(bm + wm + 16 * i) * Nn + bn + wn + 16 * j,
                acc[i][j], Nn, wmma::mem_row_major);
}

// ---------------------------------------------------------------------------
// Padding-mask decode + per-sample scaling (bool width sniffed from causal mask)
// ---------------------------------------------------------------------------
__global__ void pad_prep_kernel(const unsigned char* __restrict__ maskb,
                                const unsigned char* __restrict__ padb)
{
    __shared__ int s_cnt[NBATCH];
    __shared__ int s_mode;
    const int t = threadIdx.x;
    if (t < NBATCH) s_cnt[t] = 0;
    if (t == 0) {
        int mode = 2;                 // default: f32
        if (maskb[1] == 1)      mode = 0;   // u8
        else if (maskb[4] == 1) mode = 1;   // i32
        s_mode = mode;
    }
    __syncthreads();
    const int mode = s_mode;
    for (int i = t; i < NBATCH * L; i += blockDim.x) {
        int v;
        if (mode == 0)      v = (padb[i] != 0);
        else if (mode == 1) v = (((const int*)padb)[i] != 0);
        else                v = (((const float*)padb)[i] != 0.0f);
        g_padf[i] = (float)v;
        if (v) atomicAdd(&s_cnt[i / L], 1);
    }
    __syncthreads();
    if (t < NBATCH) g_invscale[t] = rsqrtf((float)(L - s_cnt[t]));
}

// ---------------------------------------------------------------------------
// Attention scores (unchanged from passing baseline)
// ---------------------------------------------------------------------------
template<bool CAUSAL>
__global__ void __launch_bounds__(256)
attn_score(const float* __restrict__ Q, const float* __restrict__ Kin,
           float* __restrict__ S)
{
    const int b  = blockIdx.z;
    const int n  = b / H;
    const int h  = b % H;
    const int br = blockIdx.y << 6;
    const int bc = blockIdx.x << 6;
    const int t  = threadIdx.x;
    const int ty = t >> 4, tx = t & 15;

    float* Sb = S + (size_t)b * L * L;

    if (CAUSAL && bc > br) {
        const float4 m4 = {-1e30f, -1e30f, -1e30f, -1e30f};
#pragma unroll
        for (int i = 0; i < 4; ++i)
            *(float4*)(Sb + (size_t)(br + (ty << 2) + i) * L + bc + (tx << 2)) = m4;
        return;
    }

    const float* Qb = Q   + (size_t)n * L * D + h * DH;
    const float* Kb = Kin + (size_t)n * L * D + h * DH;

    __shared__ float Qs[16][64];
    __shared__ float Ks[16][64];
    const int lr = t >> 2;
    const int lc = (t & 3) << 2;

    float acc[4][4] = {};
#pragma unroll
    for (int k0 = 0; k0 < DH; k0 += 16) {
        float4 qv = *(const float4*)(Qb + (size_t)(br + lr) * D + k0 + lc);
        float4 kv = *(const float4*)(Kb + (size_t)(bc + lr) * D + k0 + lc);
        Qs[lc + 0][lr] = qv.x; Qs[lc + 1][lr] = qv.y;
        Qs[lc + 2][lr] = qv.z; Qs[lc + 3][lr] = qv.w;
        Ks[lc + 0][lr] = kv.x; Ks[lc + 1][lr] = kv.y;
        Ks[lc + 2][lr] = kv.z; Ks[lc + 3][lr] = kv.w;
        __syncthreads();
#pragma unroll
        for (int kk = 0; kk < 16; ++kk) {
            float4 a4 = *(const float4*)&Qs[kk][ty << 2];
            float4 b4 = *(const float4*)&Ks[kk][tx << 2];
            float a[4] = {a4.x, a4.y, a4.z, a4.w};
            float c[4] = {b4.x, b4.y, b4.z, b4.w};
#pragma unroll
            for (int i = 0; i < 4; ++i)
#pragma unroll
                for (int j = 0; j < 4; ++j)
                    acc[i][j] = fmaf(a[i], c[j], acc[i][j]);
        }
        __syncthreads();
    }

    const float inv = g_invscale[n];
#pragma unroll
    for (int i = 0; i < 4; ++i) {
        const int row = br + (ty << 2) + i;
#pragma unroll
        for (int j = 0; j < 4; ++j) {
            const int col = bc + (tx << 2) + j;
            float sc = acc[i][j] * inv;
            if (CAUSAL && col > row) sc = -1e30f;
            if (g_padf[n * L + col] != 0.f) sc = -1e30f;
            acc[i][j] = sc;
        }
        float4 v = {acc[i][0], acc[i][1], acc[i][2], acc[i][3]};
        *(float4*)(Sb + (size_t)row * L + bc + (tx << 2)) = v;
    }
}

// ---------------------------------------------------------------------------
// Row softmax over length L (in-place), one 128-thread block per row.
// ---------------------------------------------------------------------------
__global__ void __launch_bounds__(128)
softmax_rows(float* __restrict__ S)
{
    float* p = S + (size_t)blockIdx.x * L;
    const int t = threadIdx.x;

    float v[8];
#pragma unroll
    for (int i = 0; i < 8; ++i) v[i] = p[t + (i << 7)];

    float m = v[0];
#pragma unroll
    for (int i = 1; i < 8; ++i) m = fmaxf(m, v[i]);

    __shared__ float red[4];
#pragma unroll
    for (int o = 16; o; o >>= 1) m = fmaxf(m, __shfl_xor_sync(0xffffffffu, m, o));
    if ((t & 31) == 0) red[t >> 5] = m;
    __syncthreads();
    m = fmaxf(fmaxf(red[0], red[1]), fmaxf(red[2], red[3]));
    __syncthreads();

    float s = 0.f;
#pragma unroll
    for (int i = 0; i < 8; ++i) { v[i] = __expf(v[i] - m); s += v[i]; }
#pragma unroll
    for (int o = 16; o; o >>= 1) s += __shfl_xor_sync(0xffffffffu, s, o);
    if ((t & 31) == 0) red[t >> 5] = s;
    __syncthreads();
    s = red[0] + red[1] + red[2] + red[3];

    const float invs = 1.f / s;
#pragma unroll
    for (int i = 0; i < 8; ++i) p[t + (i << 7)] = v[i] * invs;
}

// ---------------------------------------------------------------------------
// Attention output: O_b = P_b (L x L) * V_b (L x DH), batched over b.
// ---------------------------------------------------------------------------
__global__ void __launch_bounds__(256)
attn_out(const float* __restrict__ S, const float* __restrict__ V,
         float* __restrict__ O)
{
    const int b  = blockIdx.y;
    const int n  = b / H;
    const int h  = b % H;
    const int br = blockIdx.x << 6;

    const float* Sb = S + (size_t)b * L * L;
    const float* Vb = V + (size_t)n * L * D + h * DH;
    float*       Ob = O + (size_t)n * L * D + h * DH;

    __shared__ float Ps[32][64];
    __shared__ float Vs[32][64];

    const int t  = threadIdx.x;
    const int ty = t >> 4, tx = t & 15;
    const int plr = t >> 2, plc = (t & 3) << 3;
    const int vlr = t >> 3, vlc = (t & 7) << 3;

    float acc[4][4] = {};
    for (int k0 = 0; k0 < L; k0 += 32) {
        float4 p0 = *(const float4*)(Sb + (size_t)(br + plr) * L + k0 + plc);
        float4 p1 = *(const float4*)(Sb + (size_t)(br + plr) * L + k0 + plc + 4);
        Ps[plc + 0][plr] = p0.x; Ps[plc + 1][plr] = p0.y;
        Ps[plc + 2][plr] = p0.z; Ps[plc + 3][plr] = p0.w;
        Ps[plc + 4][plr] = p1.x; Ps[plc + 5][plr] = p1.y;
        Ps[plc + 6][plr] = p1.z; Ps[plc + 7][plr] = p1.w;
        float4 v0 = *(const float4*)(Vb + (size_t)(k0 + vlr) * D + vlc);
        float4 v1 = *(const float4*)(Vb + (size_t)(k0 + vlr) * D + vlc + 4);
        *(float4*)&Vs[vlr][vlc]     = v0;
        *(float4*)&Vs[vlr][vlc + 4] = v1;
        __syncthreads();

#pragma unroll
        for (int kk = 0; kk < 32; ++kk) {
            float4 a4 = *(const float4*)&Ps[kk][ty << 2];
            float4 b4 = *(const float4*)&Vs[kk][tx << 2];
            float a[4] = {a4.x, a4.y, a4.z, a4.w};
            float c[4] = {b4.x, b4.y, b4.z, b4.w};
#pragma unroll
            for (int i = 0; i < 4; ++i)
#pragma unroll
                for (int j = 0; j < 4; ++j)
                    acc[i][j] = fmaf(a[i], c[j], acc[i][j]);
        }
        __syncthreads();
    }

#pragma unroll
    for (int i = 0; i < 4; ++i) {
        float4 v = {acc[i][0], acc[i][1], acc[i][2], acc[i][3]};
        *(float4*)(Ob + (size_t)(br + (ty << 2) + i) * D + (tx << 2)) = v;
    }
}

// ---------------------------------------------------------------------------
// Fused residual add (+optional bias) + LayerNorm
// ---------------------------------------------------------------------------
__device__ __forceinline__ float block_sum_256(float v, float* red)
{
#pragma unroll
    for (int o = 16; o; o >>= 1) v += __shfl_xor_sync(0xffffffffu, v, o);
    const int t = threadIdx.x;
    if ((t & 31) == 0) red[t >> 5] = v;
    __syncthreads();
    float s = red[0];
#pragma unroll
    for (int i = 1; i < 8; ++i) s += red[i];
    __syncthreads();
    return s;
}

__global__ void __launch_bounds__(256)
add_ln(const float* __restrict__ A, const float* __restrict__ R,
       const float* __restrict__ bias,   // optional per-column bias (len D) or null
       const float* __restrict__ gam, const float* __restrict__ bet,
       float* __restrict__ Y)
{
    const int row = blockIdx.x;
    const float* a = A + (size_t)row * D;
    const float* r = R + (size_t)row * D;
    float*       y = Y + (size_t)row * D;

    __shared__ float xs[D];
    __shared__ float red[8];
    const int t = threadIdx.x;

    float lsum = 0.f;
    for (int i = t; i < D; i += 256) {
        float v = a[i] + r[i];
        if (bias) v += bias[i];
        xs[i] = v;
        lsum += v;
    }
    const float mu = block_sum_256(lsum, red) * (1.f / D);

    float lvar = 0.f;
    for (int i = t; i < D; i += 256) {
        const float d = xs[i] - mu;
        lvar += d * d;
    }
    const float var = block_sum_256(lvar, red) * (1.f / D);
    const float sdev = rsqrtf(var + 1e-5f);

    for (int i = t; i < D; i += 256)
        y[i] = (xs[i] - mu) * sdev * gam[i] + bet[i];
}

// ---------------------------------------------------------------------------
// Launch
// ---------------------------------------------------------------------------
extern "C" void kernel_launch(void* const* d_in, const int* in_sizes, int n_in,
                              void* d_out, int out_size)
{
    (void)in_sizes; (void)n_in; (void)out_size;

    const float* encoded = (const float*)d_in[0];
    const float* Yin     = (const float*)d_in[1];
    const unsigned char* maskb = (const unsigned char*)d_in[2];
    const unsigned char* padb  = (const unsigned char*)d_in[3];
    const float* Wq1 = (const float*)d_in[4];
    const float* Wk1 = (const float*)d_in[5];
    const float* Wv1 = (const float*)d_in[6];
    const float* ga1 = (const float*)d_in[7];
    const float* bb1 = (const float*)d_in[8];
    const float* Wq2 = (const float*)d_in[9];
    const float* Wk2 = (const float*)d_in[10];
    const float* Wv2 = (const float*)d_in[11];
    const float* ga2 = (const float*)d_in[12];
    const float* bb2 = (const float*)d_in[13];
    const float* We  = (const float*)d_in[14];
    const float* be  = (const float*)d_in[15];
    const float* Wc  = (const float*)d_in[16];
    const float* bc  = (const float*)d_in[17];
    const float* ga3 = (const float*)d_in[18];
    const float* bb3 = (const float*)d_in[19];
    float* out = (float*)d_out;

    float *pq, *pk, *pv, *pa, *py1, *py2, *ph, *ps;
    __nv_bfloat16 *pahi, *palo, *pbhi, *pblo;
    cudaGetSymbolAddress((void**)&pq,  g_q);
    cudaGetSymbolAddress((void**)&pk,  g_k);
    cudaGetSymbolAddress((void**)&pv,  g_v);
    cudaGetSymbolAddress((void**)&pa,  g_attn);
    cudaGetSymbolAddress((void**)&py1, g_y1);
    cudaGetSymbolAddress((void**)&py2, g_y2);
    cudaGetSymbolAddress((void**)&ph,  g_h);
    cudaGetSymbolAddress((void**)&ps,  g_s);
    cudaGetSymbolAddress((void**)&pahi, g_ahi);
    cudaGetSymbolAddress((void**)&palo, g_alo);
    cudaGetSymbolAddress((void**)&pbhi, g_bhi);
    cudaGetSymbolAddress((void**)&pblo, g_blo);

    cudaFuncSetAttribute(wmma_gemm, cudaFuncAttributeMaxDynamicSharedMemorySize,
                         GEMM_SMEM_BYTES);

    pad_prep_kernel<<<1, 256>>>(maskb, padb);

    const dim3 gScore(L / 64, L / 64, NHB);        // (16, 16, 64)
    const dim3 gOut(L / 64, NHB);                  // (16, 64)
    const dim3 gP(D / 128, MROWS / 128);           // projections: (8, 32)
    const dim3 gF1(DFF / 128, MROWS / 128);        // FFN1: (32, 32)
    const dim3 gF2(D / 128, MROWS / 128);          // FFN2: (8, 32)

    auto convA = [&](const float* x, int n) {
        f32_to_bf16hl<<<(n / 4 + 255) / 256, 256>>>(x, pahi, palo, n / 4);
    };
    auto convB = [&](const float* x, int n) {
        f32_to_bf16hl<<<(n / 4 + 255) / 256, 256>>>(x, pbhi, pblo, n / 4);
    };

    // ---- masked self-attention + residual + LN ----
    convA(Yin, MROWS * D);
    convB(Wq1, D * D);
    wmma_gemm<<<gP, 256, GEMM_SMEM_BYTES>>>(pahi, palo, pbhi, pblo, pq, MROWS, D, D);
    convB(Wk1, D * D);
    wmma_gemm<<<gP, 256, GEMM_SMEM_BYTES>>>(pahi, palo, pbhi, pblo, pk, MROWS, D, D);
    convB(Wv1, D * D);
    wmma_gemm<<<gP, 256, GEMM_SMEM_BYTES>>>(pahi, palo, pbhi, pblo, pv, MROWS, D, D);
    attn_score<true><<<gScore, 256>>>(pq, pk, ps);
    softmax_rows<<<NHB * L, 128>>>(ps);
    attn_out<<<gOut, 256>>>(ps, pv, pa);
    add_ln<<<MROWS, 256>>>(pa, Yin, nullptr, ga1, bb1, py1);

    // ---- cross-attention + residual + LN ----
    convA(py1, MROWS * D);
    convB(Wq2, D * D);
    wmma_gemm<<<gP, 256, GEMM_SMEM_BYTES>>>(pahi, palo, pbhi, pblo, pq, MROWS, D, D);
    convA(encoded, MROWS * D);
    convB(Wk2, D * D);
    wmma_gemm<<<gP, 256, GEMM_SMEM_BYTES>>>(pahi, palo, pbhi, pblo, pk, MROWS, D, D);
    convB(Wv2, D * D);
    wmma_gemm<<<gP, 256, GEMM_SMEM_BYTES>>>(pahi, palo, pbhi, pblo, pv, MROWS, D, D);
    attn_score<false><<<gScore, 256>>>(pq, pk, ps);
    softmax_rows<<<NHB * L, 128>>>(ps);
    attn_out<<<gOut, 256>>>(ps, pv, pa);
    add_ln<<<MROWS, 256>>>(pa, py1, nullptr, ga2, bb2, py2);

    // ---- FFN + residual + LN ----
    convA(py2, MROWS * D);
    convB(We, DFF * D);
    wmma_gemm<<<gF1, 256, GEMM_SMEM_BYTES>>>(pahi, palo, pbhi, pblo, ph, MROWS, DFF, D);
    // bias + ReLU fused into the split-conversion of FFN1's output
    f32_to_bf16hl_br<<<(MROWS * DFF / 4 + 255) / 256, 256>>>(ph, be, pahi, palo,
                                                             MROWS * DFF / 4, DFF / 4);
    convB(Wc, D * DFF);
    wmma_gemm<<<gF2, 256, GEMM_SMEM_BYTES>>>(pahi, palo, pbhi, pblo, pa, MROWS, D, DFF);
    // FFN2 bias fused into final add+LN
    add_ln<<<MROWS, 256>>>(pa, py2, bc, ga3, bb3, out);
}

// round 13
// speedup vs baseline: 1.6430x; 1.0719x over previous
#include <cuda_runtime.h>
#include <cuda_bf16.h>
#include <mma.h>
#include <math.h>
#include <stdint.h>

using namespace nvcuda;

// ---------------------------------------------------------------------------
// Problem constants (fixed shapes)
// ---------------------------------------------------------------------------
namespace {
constexpr int NBATCH = 4;
constexpr int L      = 1024;
constexpr int H      = 16;
constexpr int DH     = 64;
constexpr int D      = 1024;   // H * DH
constexpr int DFF    = 4096;
constexpr int NHB    = NBATCH * H;   // 64 attention batches
constexpr int MROWS  = NBATCH * L;   // 4096 token rows

// wmma GEMM tiling
constexpr int BK   = 32;             // K elems per stage
constexpr int BKP  = 40;             // smem row pitch in bf16 elems (80B, 16B-mult)
constexpr int STAGE_ELEMS = 128 * BKP;            // one array, one stage
constexpr int GEMM_SMEM_BYTES = 4 * 2 * STAGE_ELEMS * 2;  // 4 arrays x 2 stages x 2B = 81920
}

// ---------------------------------------------------------------------------
// Scratch (static device globals — no allocation in kernel_launch)
// ---------------------------------------------------------------------------
__device__ float g_q   [NBATCH * L * D];
__device__ float g_k   [NBATCH * L * D];
__device__ float g_v   [NBATCH * L * D];
__device__ float g_attn[NBATCH * L * D];
__device__ float g_y1  [NBATCH * L * D];
__device__ float g_y2  [NBATCH * L * D];
__device__ float g_h   [NBATCH * L * DFF];
__device__ float g_s   [(size_t)NHB * L * L];   // 256 MB score/prob matrix
__device__ float g_padf[NBATCH * L];            // padding mask as float 0/1
__device__ float g_invscale[NBATCH];            // 1/sqrt(valid_len)

// bf16 split-precision operand buffers
__device__ __nv_bfloat16 g_ahi[(size_t)MROWS * DFF];
__device__ __nv_bfloat16 g_alo[(size_t)MROWS * DFF];
__device__ __nv_bfloat16 g_bhi[(size_t)DFF * D];
__device__ __nv_bfloat16 g_blo[(size_t)DFF * D];

// ---------------------------------------------------------------------------
// cp.async helpers
// ---------------------------------------------------------------------------
__device__ __forceinline__ void cp16(void* dst_smem, const void* src_gmem)
{
    uint32_t d = (uint32_t)__cvta_generic_to_shared(dst_smem);
    asm volatile("cp.async.cg.shared.global [%0], [%1], 16;" :: "r"(d), "l"(src_gmem));
}
__device__ __forceinline__ void cp_commit()
{
    asm volatile("cp.async.commit_group;");
}
template<int N>
__device__ __forceinline__ void cp_wait()
{
    asm volatile("cp.async.wait_group %0;" :: "n"(N));
}

// ---------------------------------------------------------------------------
// fp32 -> (bf16 hi, bf16 lo) split conversion, vectorized by 4
// ---------------------------------------------------------------------------
__device__ __forceinline__ void split1(float x, __nv_bfloat16& h, __nv_bfloat16& l)
{
    h = __float2bfloat16_rn(x);
    l = __float2bfloat16_rn(x - __bfloat162float(h));
}

__global__ void __launch_bounds__(256)
f32_to_bf16hl(const float* __restrict__ x, __nv_bfloat16* __restrict__ hi,
              __nv_bfloat16* __restrict__ lo, int n4)
{
    int i = blockIdx.x * blockDim.x + threadIdx.x;
    if (i >= n4) return;
    float4 v = ((const float4*)x)[i];
    __nv_bfloat16 h0, h1, h2, h3, l0, l1, l2, l3;
    split1(v.x, h0, l0); split1(v.y, h1, l1);
    split1(v.z, h2, l2); split1(v.w, h3, l3);
    __nv_bfloat162* hp = (__nv_bfloat162*)hi;
    __nv_bfloat162* lp = (__nv_bfloat162*)lo;
    hp[2*i]   = __nv_bfloat162(h0, h1);
    hp[2*i+1] = __nv_bfloat162(h2, h3);
    lp[2*i]   = __nv_bfloat162(l0, l1);
    lp[2*i+1] = __nv_bfloat162(l2, l3);
}

// Variant with fused bias + ReLU (for FFN1 output -> FFN2 input). ncols4 = row len / 4.
__global__ void __launch_bounds__(256)
f32_to_bf16hl_br(const float* __restrict__ x, const float* __restrict__ bias,
                 __nv_bfloat16* __restrict__ hi, __nv_bfloat16* __restrict__ lo,
                 int n4, int ncols4)
{
    int i = blockIdx.x * blockDim.x + threadIdx.x;
    if (i >= n4) return;
    float4 v = ((const float4*)x)[i];
    const float4 bb = ((const float4*)bias)[i % ncols4];
    v.x = fmaxf(v.x + bb.x, 0.f); v.y = fmaxf(v.y + bb.y, 0.f);
    v.z = fmaxf(v.z + bb.z, 0.f); v.w = fmaxf(v.w + bb.w, 0.f);
    __nv_bfloat16 h0, h1, h2, h3, l0, l1, l2, l3;
    split1(v.x, h0, l0); split1(v.y, h1, l1);
    split1(v.z, h2, l2); split1(v.w, h3, l3);
    __nv_bfloat162* hp = (__nv_bfloat162*)hi;
    __nv_bfloat162* lp = (__nv_bfloat162*)lo;
    hp[2*i]   = __nv_bfloat162(h0, h1);
    hp[2*i+1] = __nv_bfloat162(h2, h3);
    lp[2*i]   = __nv_bfloat162(l0, l1);
    lp[2*i+1] = __nv_bfloat162(l2, l3);
}

// ---------------------------------------------------------------------------
// wmma bf16 split-precision GEMM (NT): C[M,Nn] = A[M,K] * B[Nn,K]^T
// A,B as bf16 hi/lo pairs (row-major, K contiguous).
// C = Ahi*Bhi + Ahi*Blo + Alo*Bhi, fp32 accumulate.
// CTA tile 128x128, 8 warps (2x4), warp tile 64x32.
// cp.async double-buffered smem, BK=32 per stage.
// __launch_bounds__(256, 2): cap regs at 128 so 2 CTAs/SM co-reside
// (R10 ncu: 136 regs -> 69,632 regs for 2 CTAs > 64K RF -> occ was 12.5%).
// Requires M%128==0, Nn%128==0, K%32==0.
// ---------------------------------------------------------------------------
__global__ void __launch_bounds__(256, 2)
wmma_gemm(const __nv_bfloat16* __restrict__ Ahi, const __nv_bfloat16* __restrict__ Alo,
          const __nv_bfloat16* __restrict__ Bhi, const __nv_bfloat16* __restrict__ Blo,
          float* __restrict__ C, int M, int Nn, int K)
{
    extern __shared__ __align__(128) __nv_bfloat16 sm[];
    __nv_bfloat16* const sAh = sm;                      // [2][128][BKP]
    __nv_bfloat16* const sAl = sm + 2 * STAGE_ELEMS;
    __nv_bfloat16* const sBh = sm + 4 * STAGE_ELEMS;
    __nv_bfloat16* const sBl = sm + 6 * STAGE_ELEMS;

    const int t   = threadIdx.x;
    const int wid = t >> 5;
    const int wm  = (wid & 1) * 64;   // warp row origin within CTA tile
    const int wn  = (wid >> 1) * 32;  // warp col origin within CTA tile
    const int bm  = blockIdx.y << 7;
    const int bn  = blockIdx.x << 7;

    // Loader mapping: row = t>>1; each thread covers 32B (2x16B) of the 64B row.
    const int lr   = t >> 1;
    const int half = (t & 1) << 4;    // elem offset 0 or 16

    const __nv_bfloat16* gAh = Ahi + (size_t)(bm + lr) * K + half;
    const __nv_bfloat16* gAl = Alo + (size_t)(bm + lr) * K + half;
    const __nv_bfloat16* gBh = Bhi + (size_t)(bn + lr) * K + half;
    const __nv_bfloat16* gBl = Blo + (size_t)(bn + lr) * K + half;
    const int sOff = lr * BKP + half; // elem offset within a stage

    wmma::fragment<wmma::accumulator, 16, 16, 16, float> acc[4][2];
#pragma unroll
    for (int i = 0; i < 4; ++i)
#pragma unroll
        for (int j = 0; j < 2; ++j) wmma::fill_fragment(acc[i][j], 0.0f);

    const int nIter = K >> 5;   // K / 32

    auto issue_stage = [&](int s, int k0) {
        __nv_bfloat16* dAh = sAh + s * STAGE_ELEMS + sOff;
        __nv_bfloat16* dAl = sAl + s * STAGE_ELEMS + sOff;
        __nv_bfloat16* dBh = sBh + s * STAGE_ELEMS + sOff;
        __nv_bfloat16* dBl = sBl + s * STAGE_ELEMS + sOff;
        cp16(dAh,     gAh + k0);
        cp16(dAh + 8, gAh + k0 + 8);
        cp16(dAl,     gAl + k0);
        cp16(dAl + 8, gAl + k0 + 8);
        cp16(dBh,     gBh + k0);
        cp16(dBh + 8, gBh + k0 + 8);
        cp16(dBl,     gBl + k0);
        cp16(dBl + 8, gBl + k0 + 8);
    };

    // Prologue: stage 0 in flight.
    issue_stage(0, 0);
    cp_commit();

    for (int it = 0; it < nIter; ++it) {
        if (it + 1 < nIter) {
            issue_stage((it + 1) & 1, (it + 1) * BK);
            cp_commit();
            cp_wait<1>();     // oldest group (current stage) complete
        } else {
            cp_wait<0>();     // last stage: wait for everything
        }
        __syncthreads();

        const int s = it & 1;
        const __nv_bfloat16* pAh = sAh + s * STAGE_ELEMS;
        const __nv_bfloat16* pAl = sAl + s * STAGE_ELEMS;
        const __nv_bfloat16* pBh = sBh + s * STAGE_ELEMS;
        const __nv_bfloat16* pBl = sBl + s * STAGE_ELEMS;

#pragma unroll
        for (int ks = 0; ks < 2; ++ks) {
            const int kc = ks * 16;
            wmma::fragment<wmma::matrix_b, 16, 16, 16, __nv_bfloat16, wmma::col_major> bh[2], bl[2];
#pragma unroll
            for (int j = 0; j < 2; ++j) {
                wmma::load_matrix_sync(bh[j], pBh + (wn + 16 * j) * BKP + kc, BKP);
                wmma::load_matrix_sync(bl[j], pBl + (wn + 16 * j) * BKP + kc, BKP);
            }
#pragma unroll
            for (int i = 0; i < 4; ++i) {
                wmma::fragment<wmma::matrix_a, 16, 16, 16, __nv_bfloat16, wmma::row_major> ah, al;
                wmma::load_matrix_sync(ah, pAh + (wm + 16 * i) * BKP + kc, BKP);
                wmma::load_matrix_sync(al, pAl + (wm + 16 * i) * BKP + kc, BKP);
#pragma unroll
                for (int j = 0; j < 2; ++j) {
                    wmma::mma_sync(acc[i][j], ah, bh[j], acc[i][j]);
                    wmma::mma_sync(acc[i][j], ah, bl[j], acc[i][j]);
                    wmma::mma_sync(acc[i][j], al, bh[j], acc[i][j]);
                }
            }
        }
        __syncthreads();   // stage fully consumed before it is overwritten
    }

#pragma unroll
    for (int i = 0; i < 4; ++i)
#pragma unroll
        for (int j = 0; j < 2; ++j)
            wmma::store_matrix_sync(
                C + (size_t)(bm + wm + 16 * i) * Nn + bn + wn + 16 * j,
                acc[i][j], Nn, wmma::mem_row_major);
}

// ---------------------------------------------------------------------------
// Padding-mask decode + per-sample scaling (bool width sniffed from causal mask)
// ---------------------------------------------------------------------------
__global__ void pad_prep_kernel(const unsigned char* __restrict__ maskb,
                                const unsigned char* __restrict__ padb)
{
    __shared__ int s_cnt[NBATCH];
    __shared__ int s_mode;
    const int t = threadIdx.x;
    if (t < NBATCH) s_cnt[t] = 0;
    if (t == 0) {
        int mode = 2;                 // default: f32
        if (maskb[1] == 1)      mode = 0;   // u8
        else if (maskb[4] == 1) mode = 1;   // i32
        s_mode = mode;
    }
    __syncthreads();
    const int mode = s_mode;
    for (int i = t; i < NBATCH * L; i += blockDim.x) {
        int v;
        if (mode == 0)      v = (padb[i] != 0);
        else if (mode == 1) v = (((const int*)padb)[i] != 0);
        else                v = (((const float*)padb)[i] != 0.0f);
        g_padf[i] = (float)v;
        if (v) atomicAdd(&s_cnt[i / L], 1);
    }
    __syncthreads();
    if (t < NBATCH) g_invscale[t] = rsqrtf((float)(L - s_cnt[t]));
}

// ---------------------------------------------------------------------------
// Attention scores (unchanged from passing baseline)
// ---------------------------------------------------------------------------
template<bool CAUSAL>
__global__ void __launch_bounds__(256)
attn_score(const float* __restrict__ Q, const float* __restrict__ Kin,
           float* __restrict__ S)
{
    const int b  = blockIdx.z;
    const int n  = b / H;
    const int h  = b % H;
    const int br = blockIdx.y << 6;
    const int bc = blockIdx.x << 6;
    const int t  = threadIdx.x;
    const int ty = t >> 4, tx = t & 15;

    float* Sb = S + (size_t)b * L * L;

    if (CAUSAL && bc > br) {
        const float4 m4 = {-1e30f, -1e30f, -1e30f, -1e30f};
#pragma unroll
        for (int i = 0; i < 4; ++i)
            *(float4*)(Sb + (size_t)(br + (ty << 2) + i) * L + bc + (tx << 2)) = m4;
        return;
    }

    const float* Qb = Q   + (size_t)n * L * D + h * DH;
    const float* Kb = Kin + (size_t)n * L * D + h * DH;

    __shared__ float Qs[16][64];
    __shared__ float Ks[16][64];
    const int lr = t >> 2;
    const int lc = (t & 3) << 2;

    float acc[4][4] = {};
#pragma unroll
    for (int k0 = 0; k0 < DH; k0 += 16) {
        float4 qv = *(const float4*)(Qb + (size_t)(br + lr) * D + k0 + lc);
        float4 kv = *(const float4*)(Kb + (size_t)(bc + lr) * D + k0 + lc);
        Qs[lc + 0][lr] = qv.x; Qs[lc + 1][lr] = qv.y;
        Qs[lc + 2][lr] = qv.z; Qs[lc + 3][lr] = qv.w;
        Ks[lc + 0][lr] = kv.x; Ks[lc + 1][lr] = kv.y;
        Ks[lc + 2][lr] = kv.z; Ks[lc + 3][lr] = kv.w;
        __syncthreads();
#pragma unroll
        for (int kk = 0; kk < 16; ++kk) {
            float4 a4 = *(const float4*)&Qs[kk][ty << 2];
            float4 b4 = *(const float4*)&Ks[kk][tx << 2];
            float a[4] = {a4.x, a4.y, a4.z, a4.w};
            float c[4] = {b4.x, b4.y, b4.z, b4.w};
#pragma unroll
            for (int i = 0; i < 4; ++i)
#pragma unroll
                for (int j = 0; j < 4; ++j)
                    acc[i][j] = fmaf(a[i], c[j], acc[i][j]);
        }
        __syncthreads();
    }

    const float inv = g_invscale[n];
#pragma unroll
    for (int i = 0; i < 4; ++i) {
        const int row = br + (ty << 2) + i;
#pragma unroll
        for (int j = 0; j < 4; ++j) {
            const int col = bc + (tx << 2) + j;
            float sc = acc[i][j] * inv;
            if (CAUSAL && col > row) sc = -1e30f;
            if (g_padf[n * L + col] != 0.f) sc = -1e30f;
            acc[i][j] = sc;
        }
        float4 v = {acc[i][0], acc[i][1], acc[i][2], acc[i][3]};
        *(float4*)(Sb + (size_t)row * L + bc + (tx << 2)) = v;
    }
}

// ---------------------------------------------------------------------------
// Row softmax over length L (in-place), one 128-thread block per row.
// ---------------------------------------------------------------------------
__global__ void __launch_bounds__(128)
softmax_rows(float* __restrict__ S)
{
    float* p = S + (size_t)blockIdx.x * L;
    const int t = threadIdx.x;

    float v[8];
#pragma unroll
    for (int i = 0; i < 8; ++i) v[i] = p[t + (i << 7)];

    float m = v[0];
#pragma unroll
    for (int i = 1; i < 8; ++i) m = fmaxf(m, v[i]);

    __shared__ float red[4];
#pragma unroll
    for (int o = 16; o; o >>= 1) m = fmaxf(m, __shfl_xor_sync(0xffffffffu, m, o));
    if ((t & 31) == 0) red[t >> 5] = m;
    __syncthreads();
    m = fmaxf(fmaxf(red[0], red[1]), fmaxf(red[2], red[3]));
    __syncthreads();

    float s = 0.f;
#pragma unroll
    for (int i = 0; i < 8; ++i) { v[i] = __expf(v[i] - m); s += v[i]; }
#pragma unroll
    for (int o = 16; o; o >>= 1) s += __shfl_xor_sync(0xffffffffu, s, o);
    if ((t & 31) == 0) red[t >> 5] = s;
    __syncthreads();
    s = red[0] + red[1] + red[2] + red[3];

    const float invs = 1.f / s;
#pragma unroll
    for (int i = 0; i < 8; ++i) p[t + (i << 7)] = v[i] * invs;
}

// ---------------------------------------------------------------------------
// Attention output: O_b = P_b (L x L) * V_b (L x DH), batched over b.
// ---------------------------------------------------------------------------
__global__ void __launch_bounds__(256)
attn_out(const float* __restrict__ S, const float* __restrict__ V,
         float* __restrict__ O)
{
    const int b  = blockIdx.y;
    const int n  = b / H;
    const int h  = b % H;
    const int br = blockIdx.x << 6;

    const float* Sb = S + (size_t)b * L * L;
    const float* Vb = V + (size_t)n * L * D + h * DH;
    float*       Ob = O + (size_t)n * L * D + h * DH;

    __shared__ float Ps[32][64];
    __shared__ float Vs[32][64];

    const int t  = threadIdx.x;
    const int ty = t >> 4, tx = t & 15;
    const int plr = t >> 2, plc = (t & 3) << 3;
    const int vlr = t >> 3, vlc = (t & 7) << 3;

    float acc[4][4] = {};
    for (int k0 = 0; k0 < L; k0 += 32) {
        float4 p0 = *(const float4*)(Sb + (size_t)(br + plr) * L + k0 + plc);
        float4 p1 = *(const float4*)(Sb + (size_t)(br + plr) * L + k0 + plc + 4);
        Ps[plc + 0][plr] = p0.x; Ps[plc + 1][plr] = p0.y;
        Ps[plc + 2][plr] = p0.z; Ps[plc + 3][plr] = p0.w;
        Ps[plc + 4][plr] = p1.x; Ps[plc + 5][plr] = p1.y;
        Ps[plc + 6][plr] = p1.z; Ps[plc + 7][plr] = p1.w;
        float4 v0 = *(const float4*)(Vb + (size_t)(k0 + vlr) * D + vlc);
        float4 v1 = *(const float4*)(Vb + (size_t)(k0 + vlr) * D + vlc + 4);
        *(float4*)&Vs[vlr][vlc]     = v0;
        *(float4*)&Vs[vlr][vlc + 4] = v1;
        __syncthreads();

#pragma unroll
        for (int kk = 0; kk < 32; ++kk) {
            float4 a4 = *(const float4*)&Ps[kk][ty << 2];
            float4 b4 = *(const float4*)&Vs[kk][tx << 2];
            float a[4] = {a4.x, a4.y, a4.z, a4.w};
            float c[4] = {b4.x, b4.y, b4.z, b4.w};
#pragma unroll
            for (int i = 0; i < 4; ++i)
#pragma unroll
                for (int j = 0; j < 4; ++j)
                    acc[i][j] = fmaf(a[i], c[j], acc[i][j]);
        }
        __syncthreads();
    }

#pragma unroll
    for (int i = 0; i < 4; ++i) {
        float4 v = {acc[i][0], acc[i][1], acc[i][2], acc[i][3]};
        *(float4*)(Ob + (size_t)(br + (ty << 2) + i) * D + (tx << 2)) = v;
    }
}

// ---------------------------------------------------------------------------
// Fused residual add (+optional bias) + LayerNorm
// ---------------------------------------------------------------------------
__device__ __forceinline__ float block_sum_256(float v, float* red)
{
#pragma unroll
    for (int o = 16; o; o >>= 1) v += __shfl_xor_sync(0xffffffffu, v, o);
    const int t = threadIdx.x;
    if ((t & 31) == 0) red[t >> 5] = v;
    __syncthreads();
    float s = red[0];
#pragma unroll
    for (int i = 1; i < 8; ++i) s += red[i];
    __syncthreads();
    return s;
}

__global__ void __launch_bounds__(256)
add_ln(const float* __restrict__ A, const float* __restrict__ R,
       const float* __restrict__ bias,   // optional per-column bias (len D) or null
       const float* __restrict__ gam, const float* __restrict__ bet,
       float* __restrict__ Y)
{
    const int row = blockIdx.x;
    const float* a = A + (size_t)row * D;
    const float* r = R + (size_t)row * D;
    float*       y = Y + (size_t)row * D;

    __shared__ float xs[D];
    __shared__ float red[8];
    const int t = threadIdx.x;

    float lsum = 0.f;
    for (int i = t; i < D; i += 256) {
        float v = a[i] + r[i];
        if (bias) v += bias[i];
        xs[i] = v;
        lsum += v;
    }
    const float mu = block_sum_256(lsum, red) * (1.f / D);

    float lvar = 0.f;
    for (int i = t; i < D; i += 256) {
        const float d = xs[i] - mu;
        lvar += d * d;
    }
    const float var = block_sum_256(lvar, red) * (1.f / D);
    const float sdev = rsqrtf(var + 1e-5f);

    for (int i = t; i < D; i += 256)
        y[i] = (xs[i] - mu) * sdev * gam[i] + bet[i];
}

// ---------------------------------------------------------------------------
// Launch
// ---------------------------------------------------------------------------
extern "C" void kernel_launch(void* const* d_in, const int* in_sizes, int n_in,
                              void* d_out, int out_size)
{
    (void)in_sizes; (void)n_in; (void)out_size;

    const float* encoded = (const float*)d_in[0];
    const float* Yin     = (const float*)d_in[1];
    const unsigned char* maskb = (const unsigned char*)d_in[2];
    const unsigned char* padb  = (const unsigned char*)d_in[3];
    const float* Wq1 = (const float*)d_in[4];
    const float* Wk1 = (const float*)d_in[5];
    const float* Wv1 = (const float*)d_in[6];
    const float* ga1 = (const float*)d_in[7];
    const float* bb1 = (const float*)d_in[8];
    const float* Wq2 = (const float*)d_in[9];
    const float* Wk2 = (const float*)d_in[10];
    const float* Wv2 = (const float*)d_in[11];
    const float* ga2 = (const float*)d_in[12];
    const float* bb2 = (const float*)d_in[13];
    const float* We  = (const float*)d_in[14];
    const float* be  = (const float*)d_in[15];
    const float* Wc  = (const float*)d_in[16];
    const float* bc  = (const float*)d_in[17];
    const float* ga3 = (const float*)d_in[18];
    const float* bb3 = (const float*)d_in[19];
    float* out = (float*)d_out;

    float *pq, *pk, *pv, *pa, *py1, *py2, *ph, *ps;
    __nv_bfloat16 *pahi, *palo, *pbhi, *pblo;
    cudaGetSymbolAddress((void**)&pq,  g_q);
    cudaGetSymbolAddress((void**)&pk,  g_k);
    cudaGetSymbolAddress((void**)&pv,  g_v);
    cudaGetSymbolAddress((void**)&pa,  g_attn);
    cudaGetSymbolAddress((void**)&py1, g_y1);
    cudaGetSymbolAddress((void**)&py2, g_y2);
    cudaGetSymbolAddress((void**)&ph,  g_h);
    cudaGetSymbolAddress((void**)&ps,  g_s);
    cudaGetSymbolAddress((void**)&pahi, g_ahi);
    cudaGetSymbolAddress((void**)&palo, g_alo);
    cudaGetSymbolAddress((void**)&pbhi, g_bhi);
    cudaGetSymbolAddress((void**)&pblo, g_blo);

    cudaFuncSetAttribute(wmma_gemm, cudaFuncAttributeMaxDynamicSharedMemorySize,
                         GEMM_SMEM_BYTES);

    pad_prep_kernel<<<1, 256>>>(maskb, padb);

    const dim3 gScore(L / 64, L / 64, NHB);        // (16, 16, 64)
    const dim3 gOut(L / 64, NHB);                  // (16, 64)
    const dim3 gP(D / 128, MROWS / 128);           // projections: (8, 32)
    const dim3 gF1(DFF / 128, MROWS / 128);        // FFN1: (32, 32)
    const dim3 gF2(D / 128, MROWS / 128);          // FFN2: (8, 32)

    auto convA = [&](const float* x, int n) {
        f32_to_bf16hl<<<(n / 4 + 255) / 256, 256>>>(x, pahi, palo, n / 4);
    };
    auto convB = [&](const float* x, int n) {
        f32_to_bf16hl<<<(n / 4 + 255) / 256, 256>>>(x, pbhi, pblo, n / 4);
    };

    // ---- masked self-attention + residual + LN ----
    convA(Yin, MROWS * D);
    convB(Wq1, D * D);
    wmma_gemm<<<gP, 256, GEMM_SMEM_BYTES>>>(pahi, palo, pbhi, pblo, pq, MROWS, D, D);
    convB(Wk1, D * D);
    wmma_gemm<<<gP, 256, GEMM_SMEM_BYTES>>>(pahi, palo, pbhi, pblo, pk, MROWS, D, D);
    convB(Wv1, D * D);
    wmma_gemm<<<gP, 256, GEMM_SMEM_BYTES>>>(pahi, palo, pbhi, pblo, pv, MROWS, D, D);
    attn_score<true><<<gScore, 256>>>(pq, pk, ps);
    softmax_rows<<<NHB * L, 128>>>(ps);
    attn_out<<<gOut, 256>>>(ps, pv, pa);
    add_ln<<<MROWS, 256>>>(pa, Yin, nullptr, ga1, bb1, py1);

    // ---- cross-attention + residual + LN ----
    convA(py1, MROWS * D);
    convB(Wq2, D * D);
    wmma_gemm<<<gP, 256, GEMM_SMEM_BYTES>>>(pahi, palo, pbhi, pblo, pq, MROWS, D, D);
    convA(encoded, MROWS * D);
    convB(Wk2, D * D);
    wmma_gemm<<<gP, 256, GEMM_SMEM_BYTES>>>(pahi, palo, pbhi, pblo, pk, MROWS, D, D);
    convB(Wv2, D * D);
    wmma_gemm<<<gP, 256, GEMM_SMEM_BYTES>>>(pahi, palo, pbhi, pblo, pv, MROWS, D, D);
    attn_score<false><<<gScore, 256>>>(pq, pk, ps);
    softmax_rows<<<NHB * L, 128>>>(ps);
    attn_out<<<gOut, 256>>>(ps, pv, pa);
    add_ln<<<MROWS, 256>>>(pa, py1, nullptr, ga2, bb2, py2);

    // ---- FFN + residual + LN ----
    convA(py2, MROWS * D);
    convB(We, DFF * D);
    wmma_gemm<<<gF1, 256, GEMM_SMEM_BYTES>>>(pahi, palo, pbhi, pblo, ph, MROWS, DFF, D);
    // bias + ReLU fused into the split-conversion of FFN1's output
    f32_to_bf16hl_br<<<(MROWS * DFF / 4 + 255) / 256, 256>>>(ph, be, pahi, palo,
                                                             MROWS * DFF / 4, DFF / 4);
    convB(Wc, D * DFF);
    wmma_gemm<<<gF2, 256, GEMM_SMEM_BYTES>>>(pahi, palo, pbhi, pblo, pa, MROWS, D, DFF);
    // FFN2 bias fused into final add+LN
    add_ln<<<MROWS, 256>>>(pa, py2, bc, ga3, bb3, out);
}

// round 16
// speedup vs baseline: 1.6511x; 1.0050x over previous
#include <cuda_runtime.h>
#include <cuda_bf16.h>
#include <mma.h>
#include <math.h>
#include <stdint.h>

using namespace nvcuda;

// ---------------------------------------------------------------------------
// Problem constants (fixed shapes)
// ---------------------------------------------------------------------------
namespace {
constexpr int NBATCH = 4;
constexpr int L      = 1024;
constexpr int H      = 16;
constexpr int DH     = 64;
constexpr int D      = 1024;   // H * DH
constexpr int DFF    = 4096;
constexpr int NHB    = NBATCH * H;   // 64 attention batches
constexpr int MROWS  = NBATCH * L;   // 4096 token rows

// wmma GEMM tiling
constexpr int BK   = 32;             // K elems per stage
constexpr int BKP  = 40;             // smem row pitch in bf16 elems (80B, 16B-mult)
constexpr int STAGE_ELEMS = 128 * BKP;            // one array, one stage
constexpr int GEMM_SMEM_BYTES = 4 * 2 * STAGE_ELEMS * 2;  // 81920
}

// ---------------------------------------------------------------------------
// Scratch (static device globals — no allocation in kernel_launch)
// ---------------------------------------------------------------------------
__device__ float g_q   [NBATCH * L * D];
__device__ float g_k   [NBATCH * L * D];
__device__ float g_v   [NBATCH * L * D];
__device__ float g_attn[NBATCH * L * D];
__device__ float g_y1  [NBATCH * L * D];
__device__ float g_y2  [NBATCH * L * D];
__device__ float g_h   [NBATCH * L * DFF];
__device__ float g_s   [(size_t)NHB * L * L];   // 256 MB score/prob matrix
__device__ float g_padf[NBATCH * L];            // padding mask as float 0/1
__device__ float g_invscale[NBATCH];            // 1/sqrt(valid_len)

// bf16 split-precision operand buffers
__device__ __nv_bfloat16 g_ahi[(size_t)MROWS * DFF];
__device__ __nv_bfloat16 g_alo[(size_t)MROWS * DFF];
__device__ __nv_bfloat16 g_bhi[(size_t)DFF * D];
__device__ __nv_bfloat16 g_blo[(size_t)DFF * D];

// ---------------------------------------------------------------------------
// cp.async helpers
// ---------------------------------------------------------------------------
__device__ __forceinline__ void cp16(void* dst_smem, const void* src_gmem)
{
    uint32_t d = (uint32_t)__cvta_generic_to_shared(dst_smem);
    asm volatile("cp.async.cg.shared.global [%0], [%1], 16;" :: "r"(d), "l"(src_gmem));
}
__device__ __forceinline__ void cp_commit()
{
    asm volatile("cp.async.commit_group;");
}
template<int N>
__device__ __forceinline__ void cp_wait()
{
    asm volatile("cp.async.wait_group %0;" :: "n"(N));
}

// ---------------------------------------------------------------------------
// fp32 -> (bf16 hi, bf16 lo) split conversion, vectorized by 4
// ---------------------------------------------------------------------------
__device__ __forceinline__ void split1(float x, __nv_bfloat16& h, __nv_bfloat16& l)
{
    h = __float2bfloat16_rn(x);
    l = __float2bfloat16_rn(x - __bfloat162float(h));
}

__global__ void __launch_bounds__(256)
f32_to_bf16hl(const float* __restrict__ x, __nv_bfloat16* __restrict__ hi,
              __nv_bfloat16* __restrict__ lo, int n4)
{
    int i = blockIdx.x * blockDim.x + threadIdx.x;
    if (i >= n4) return;
    float4 v = ((const float4*)x)[i];
    __nv_bfloat16 h0, h1, h2, h3, l0, l1, l2, l3;
    split1(v.x, h0, l0); split1(v.y, h1, l1);
    split1(v.z, h2, l2); split1(v.w, h3, l3);
    __nv_bfloat162* hp = (__nv_bfloat162*)hi;
    __nv_bfloat162* lp = (__nv_bfloat162*)lo;
    hp[2*i]   = __nv_bfloat162(h0, h1);
    hp[2*i+1] = __nv_bfloat162(h2, h3);
    lp[2*i]   = __nv_bfloat162(l0, l1);
    lp[2*i+1] = __nv_bfloat162(l2, l3);
}

// Variant with fused bias + ReLU (for FFN1 output -> FFN2 input). ncols4 = row len / 4.
__global__ void __launch_bounds__(256)
f32_to_bf16hl_br(const float* __restrict__ x, const float* __restrict__ bias,
                 __nv_bfloat16* __restrict__ hi, __nv_bfloat16* __restrict__ lo,
                 int n4, int ncols4)
{
    int i = blockIdx.x * blockDim.x + threadIdx.x;
    if (i >= n4) return;
    float4 v = ((const float4*)x)[i];
    const float4 bb = ((const float4*)bias)[i % ncols4];
    v.x = fmaxf(v.x + bb.x, 0.f); v.y = fmaxf(v.y + bb.y, 0.f);
    v.z = fmaxf(v.z + bb.z, 0.f); v.w = fmaxf(v.w + bb.w, 0.f);
    __nv_bfloat16 h0, h1, h2, h3, l0, l1, l2, l3;
    split1(v.x, h0, l0); split1(v.y, h1, l1);
    split1(v.z, h2, l2); split1(v.w, h3, l3);
    __nv_bfloat162* hp = (__nv_bfloat162*)hi;
    __nv_bfloat162* lp = (__nv_bfloat162*)lo;
    hp[2*i]   = __nv_bfloat162(h0, h1);
    hp[2*i+1] = __nv_bfloat162(h2, h3);
    lp[2*i]   = __nv_bfloat162(l0, l1);
    lp[2*i+1] = __nv_bfloat162(l2, l3);
}

// ---------------------------------------------------------------------------
// Shared GEMM core: C[M,Nn] = A[M,K] * B[Nn,K]^T, split-bf16 3-term.
// CTA tile 128x128, 8 warps, cp.async double-buffered, BK=32 per stage.
// ---------------------------------------------------------------------------
__device__ __forceinline__ void
wmma_gemm_core(const __nv_bfloat16* __restrict__ Ahi, const __nv_bfloat16* __restrict__ Alo,
               const __nv_bfloat16* __restrict__ Bhi, const __nv_bfloat16* __restrict__ Blo,
               float* __restrict__ C, int M, int Nn, int K,
               __nv_bfloat16* sm)
{
    __nv_bfloat16* const sAh = sm;                      // [2][128][BKP]
    __nv_bfloat16* const sAl = sm + 2 * STAGE_ELEMS;
    __nv_bfloat16* const sBh = sm + 4 * STAGE_ELEMS;
    __nv_bfloat16* const sBl = sm + 6 * STAGE_ELEMS;

    const int t   = threadIdx.x;
    const int wid = t >> 5;
    const int wm  = (wid & 1) * 64;   // warp row origin within CTA tile
    const int wn  = (wid >> 1) * 32;  // warp col origin within CTA tile
    const int bm  = blockIdx.y << 7;
    const int bn  = blockIdx.x << 7;

    const int lr   = t >> 1;
    const int half = (t & 1) << 4;    // elem offset 0 or 16

    const __nv_bfloat16* gAh = Ahi + (size_t)(bm + lr) * K + half;
    const __nv_bfloat16* gAl = Alo + (size_t)(bm + lr) * K + half;
    const __nv_bfloat16* gBh = Bhi + (size_t)(bn + lr) * K + half;
    const __nv_bfloat16* gBl = Blo + (size_t)(bn + lr) * K + half;
    const int sOff = lr * BKP + half;

    wmma::fragment<wmma::accumulator, 16, 16, 16, float> acc[4][2];
#pragma unroll
    for (int i = 0; i < 4; ++i)
#pragma unroll
        for (int j = 0; j < 2; ++j) wmma::fill_fragment(acc[i][j], 0.0f);

    const int nIter = K >> 5;   // K / 32

    auto issue_stage = [&](int s, int k0) {
        __nv_bfloat16* dAh = sAh + s * STAGE_ELEMS + sOff;
        __nv_bfloat16* dAl = sAl + s * STAGE_ELEMS + sOff;
        __nv_bfloat16* dBh = sBh + s * STAGE_ELEMS + sOff;
        __nv_bfloat16* dBl = sBl + s * STAGE_ELEMS + sOff;
        cp16(dAh,     gAh + k0);
        cp16(dAh + 8, gAh + k0 + 8);
        cp16(dAl,     gAl + k0);
        cp16(dAl + 8, gAl + k0 + 8);
        cp16(dBh,     gBh + k0);
        cp16(dBh + 8, gBh + k0 + 8);
        cp16(dBl,     gBl + k0);
        cp16(dBl + 8, gBl + k0 + 8);
    };

    issue_stage(0, 0);
    cp_commit();

    for (int it = 0; it < nIter; ++it) {
        if (it + 1 < nIter) {
            issue_stage((it + 1) & 1, (it + 1) * BK);
            cp_commit();
            cp_wait<1>();
        } else {
            cp_wait<0>();
        }
        __syncthreads();

        const int s = it & 1;
        const __nv_bfloat16* pAh = sAh + s * STAGE_ELEMS;
        const __nv_bfloat16* pAl = sAl + s * STAGE_ELEMS;
        const __nv_bfloat16* pBh = sBh + s * STAGE_ELEMS;
        const __nv_bfloat16* pBl = sBl + s * STAGE_ELEMS;

#pragma unroll
        for (int ks = 0; ks < 2; ++ks) {
            const int kc = ks * 16;
            wmma::fragment<wmma::matrix_b, 16, 16, 16, __nv_bfloat16, wmma::col_major> bh[2], bl[2];
#pragma unroll
            for (int j = 0; j < 2; ++j) {
                wmma::load_matrix_sync(bh[j], pBh + (wn + 16 * j) * BKP + kc, BKP);
                wmma::load_matrix_sync(bl[j], pBl + (wn + 16 * j) * BKP + kc, BKP);
            }
#pragma unroll
            for (int i = 0; i < 4; ++i) {
                wmma::fragment<wmma::matrix_a, 16, 16, 16, __nv_bfloat16, wmma::row_major> ah, al;
                wmma::load_matrix_sync(ah, pAh + (wm + 16 * i) * BKP + kc, BKP);
                wmma::load_matrix_sync(al, pAl + (wm + 16 * i) * BKP + kc, BKP);
#pragma unroll
                for (int j = 0; j < 2; ++j) {
                    wmma::mma_sync(acc[i][j], ah, bh[j], acc[i][j]);
                    wmma::mma_sync(acc[i][j], ah, bl[j], acc[i][j]);
                    wmma::mma_sync(acc[i][j], al, bh[j], acc[i][j]);
                }
            }
        }
        __syncthreads();
    }

#pragma unroll
    for (int i = 0; i < 4; ++i)
#pragma unroll
        for (int j = 0; j < 2; ++j)
            wmma::store_matrix_sync(
                C + (size_t)(bm + wm + 16 * i) * Nn + bn + wn + 16 * j,
                acc[i][j], Nn, wmma::mem_row_major);
}

// Single-GEMM wrapper (FFN path).
__global__ void __launch_bounds__(256, 2)
wmma_gemm(const __nv_bfloat16* __restrict__ Ahi, const __nv_bfloat16* __restrict__ Alo,
          const __nv_bfloat16* __restrict__ Bhi, const __nv_bfloat16* __restrict__ Blo,
          float* __restrict__ C, int M, int Nn, int K)
{
    extern __shared__ __align__(128) __nv_bfloat16 sm[];
    wmma_gemm_core(Ahi, Alo, Bhi, Blo, C, M, Nn, K, sm);
}

// z-batched 3-GEMM wrapper (Q/K/V projections in one launch; grid.z = 3).
// Triples the resident grid vs 3 serial 256-CTA launches -> both CTA slots
// per SM stay filled (R13 ncu: occ 19.8% because 256 CTAs / 148 SMs).
struct GemmBatch3 {
    const __nv_bfloat16* Ah[3];
    const __nv_bfloat16* Al[3];
    const __nv_bfloat16* Bh[3];
    const __nv_bfloat16* Bl[3];
    float* C[3];
};

__global__ void __launch_bounds__(256, 2)
wmma_gemm_b3(GemmBatch3 b, int M, int Nn, int K)
{
    extern __shared__ __align__(128) __nv_bfloat16 sm[];
    const int z = blockIdx.z;
    wmma_gemm_core(b.Ah[z], b.Al[z], b.Bh[z], b.Bl[z], b.C[z], M, Nn, K, sm);
}

// ---------------------------------------------------------------------------
// Padding-mask decode + per-sample scaling (bool width sniffed from causal mask)
// ---------------------------------------------------------------------------
__global__ void pad_prep_kernel(const unsigned char* __restrict__ maskb,
                                const unsigned char* __restrict__ padb)
{
    __shared__ int s_cnt[NBATCH];
    __shared__ int s_mode;
    const int t = threadIdx.x;
    if (t < NBATCH) s_cnt[t] = 0;
    if (t == 0) {
        int mode = 2;                 // default: f32
        if (maskb[1] == 1)      mode = 0;   // u8
        else if (maskb[4] == 1) mode = 1;   // i32
        s_mode = mode;
    }
    __syncthreads();
    const int mode = s_mode;
    for (int i = t; i < NBATCH * L; i += blockDim.x) {
        int v;
        if (mode == 0)      v = (padb[i] != 0);
        else if (mode == 1) v = (((const int*)padb)[i] != 0);
        else                v = (((const float*)padb)[i] != 0.0f);
        g_padf[i] = (float)v;
        if (v) atomicAdd(&s_cnt[i / L], 1);
    }
    __syncthreads();
    if (t < NBATCH) g_invscale[t] = rsqrtf((float)(L - s_cnt[t]));
}

// ---------------------------------------------------------------------------
// Attention scores (unchanged from passing baseline)
// ---------------------------------------------------------------------------
template<bool CAUSAL>
__global__ void __launch_bounds__(256)
attn_score(const float* __restrict__ Q, const float* __restrict__ Kin,
           float* __restrict__ S)
{
    const int b  = blockIdx.z;
    const int n  = b / H;
    const int h  = b % H;
    const int br = blockIdx.y << 6;
    const int bc = blockIdx.x << 6;
    const int t  = threadIdx.x;
    const int ty = t >> 4, tx = t & 15;

    float* Sb = S + (size_t)b * L * L;

    if (CAUSAL && bc > br) {
        const float4 m4 = {-1e30f, -1e30f, -1e30f, -1e30f};
#pragma unroll
        for (int i = 0; i < 4; ++i)
            *(float4*)(Sb + (size_t)(br + (ty << 2) + i) * L + bc + (tx << 2)) = m4;
        return;
    }

    const float* Qb = Q   + (size_t)n * L * D + h * DH;
    const float* Kb = Kin + (size_t)n * L * D + h * DH;

    __shared__ float Qs[16][64];
    __shared__ float Ks[16][64];
    const int lr = t >> 2;
    const int lc = (t & 3) << 2;

    float acc[4][4] = {};
#pragma unroll
    for (int k0 = 0; k0 < DH; k0 += 16) {
        float4 qv = *(const float4*)(Qb + (size_t)(br + lr) * D + k0 + lc);
        float4 kv = *(const float4*)(Kb + (size_t)(bc + lr) * D + k0 + lc);
        Qs[lc + 0][lr] = qv.x; Qs[lc + 1][lr] = qv.y;
        Qs[lc + 2][lr] = qv.z; Qs[lc + 3][lr] = qv.w;
        Ks[lc + 0][lr] = kv.x; Ks[lc + 1][lr] = kv.y;
        Ks[lc + 2][lr] = kv.z; Ks[lc + 3][lr] = kv.w;
        __syncthreads();
#pragma unroll
        for (int kk = 0; kk < 16; ++kk) {
            float4 a4 = *(const float4*)&Qs[kk][ty << 2];
            float4 b4 = *(const float4*)&Ks[kk][tx << 2];
            float a[4] = {a4.x, a4.y, a4.z, a4.w};
            float c[4] = {b4.x, b4.y, b4.z, b4.w};
#pragma unroll
            for (int i = 0; i < 4; ++i)
#pragma unroll
                for (int j = 0; j < 4; ++j)
                    acc[i][j] = fmaf(a[i], c[j], acc[i][j]);
        }
        __syncthreads();
    }

    const float inv = g_invscale[n];
#pragma unroll
    for (int i = 0; i < 4; ++i) {
        const int row = br + (ty << 2) + i;
#pragma unroll
        for (int j = 0; j < 4; ++j) {
            const int col = bc + (tx << 2) + j;
            float sc = acc[i][j] * inv;
            if (CAUSAL && col > row) sc = -1e30f;
            if (g_padf[n * L + col] != 0.f) sc = -1e30f;
            acc[i][j] = sc;
        }
        float4 v = {acc[i][0], acc[i][1], acc[i][2], acc[i][3]};
        *(float4*)(Sb + (size_t)row * L + bc + (tx << 2)) = v;
    }
}

// ---------------------------------------------------------------------------
// Row softmax over length L (in-place), one 128-thread block per row.
// ---------------------------------------------------------------------------
__global__ void __launch_bounds__(128)
softmax_rows(float* __restrict__ S)
{
    float* p = S + (size_t)blockIdx.x * L;
    const int t = threadIdx.x;

    float v[8];
#pragma unroll
    for (int i = 0; i < 8; ++i) v[i] = p[t + (i << 7)];

    float m = v[0];
#pragma unroll
    for (int i = 1; i < 8; ++i) m = fmaxf(m, v[i]);

    __shared__ float red[4];
#pragma unroll
    for (int o = 16; o; o >>= 1) m = fmaxf(m, __shfl_xor_sync(0xffffffffu, m, o));
    if ((t & 31) == 0) red[t >> 5] = m;
    __syncthreads();
    m = fmaxf(fmaxf(red[0], red[1]), fmaxf(red[2], red[3]));
    __syncthreads();

    float s = 0.f;
#pragma unroll
    for (int i = 0; i < 8; ++i) { v[i] = __expf(v[i] - m); s += v[i]; }
#pragma unroll
    for (int o = 16; o; o >>= 1) s += __shfl_xor_sync(0xffffffffu, s, o);
    if ((t & 31) == 0) red[t >> 5] = s;
    __syncthreads();
    s = red[0] + red[1] + red[2] + red[3];

    const float invs = 1.f / s;
#pragma unroll
    for (int i = 0; i < 8; ++i) p[t + (i << 7)] = v[i] * invs;
}

// ---------------------------------------------------------------------------
// Attention output: O_b = P_b (L x L) * V_b (L x DH), batched over b.
// ---------------------------------------------------------------------------
__global__ void __launch_bounds__(256)
attn_out(const float* __restrict__ S, const float* __restrict__ V,
         float* __restrict__ O)
{
    const int b  = blockIdx.y;
    const int n  = b / H;
    const int h  = b % H;
    const int br = blockIdx.x << 6;

    const float* Sb = S + (size_t)b * L * L;
    const float* Vb = V + (size_t)n * L * D + h * DH;
    float*       Ob = O + (size_t)n * L * D + h * DH;

    __shared__ float Ps[32][64];
    __shared__ float Vs[32][64];

    const int t  = threadIdx.x;
    const int ty = t >> 4, tx = t & 15;
    const int plr = t >> 2, plc = (t & 3) << 3;
    const int vlr = t >> 3, vlc = (t & 7) << 3;

    float acc[4][4] = {};
    for (int k0 = 0; k0 < L; k0 += 32) {
        float4 p0 = *(const float4*)(Sb + (size_t)(br + plr) * L + k0 + plc);
        float4 p1 = *(const float4*)(Sb + (size_t)(br + plr) * L + k0 + plc + 4);
        Ps[plc + 0][plr] = p0.x; Ps[plc + 1][plr] = p0.y;
        Ps[plc + 2][plr] = p0.z; Ps[plc + 3][plr] = p0.w;
        Ps[plc + 4][plr] = p1.x; Ps[plc + 5][plr] = p1.y;
        Ps[plc + 6][plr] = p1.z; Ps[plc + 7][plr] = p1.w;
        float4 v0 = *(const float4*)(Vb + (size_t)(k0 + vlr) * D + vlc);
        float4 v1 = *(const float4*)(Vb + (size_t)(k0 + vlr) * D + vlc + 4);
        *(float4*)&Vs[vlr][vlc]     = v0;
        *(float4*)&Vs[vlr][vlc + 4] = v1;
        __syncthreads();

#pragma unroll
        for (int kk = 0; kk < 32; ++kk) {
            float4 a4 = *(const float4*)&Ps[kk][ty << 2];
            float4 b4 = *(const float4*)&Vs[kk][tx << 2];
            float a[4] = {a4.x, a4.y, a4.z, a4.w};
            float c[4] = {b4.x, b4.y, b4.z, b4.w};
#pragma unroll
            for (int i = 0; i < 4; ++i)
#pragma unroll
                for (int j = 0; j < 4; ++j)
                    acc[i][j] = fmaf(a[i], c[j], acc[i][j]);
        }
        __syncthreads();
    }

#pragma unroll
    for (int i = 0; i < 4; ++i) {
        float4 v = {acc[i][0], acc[i][1], acc[i][2], acc[i][3]};
        *(float4*)(Ob + (size_t)(br + (ty << 2) + i) * D + (tx << 2)) = v;
    }
}

// ---------------------------------------------------------------------------
// Fused residual add (+optional bias) + LayerNorm
// ---------------------------------------------------------------------------
__device__ __forceinline__ float block_sum_256(float v, float* red)
{
#pragma unroll
    for (int o = 16; o; o >>= 1) v += __shfl_xor_sync(0xffffffffu, v, o);
    const int t = threadIdx.x;
    if ((t & 31) == 0) red[t >> 5] = v;
    __syncthreads();
    float s = red[0];
#pragma unroll
    for (int i = 1; i < 8; ++i) s += red[i];
    __syncthreads();
    return s;
}

__global__ void __launch_bounds__(256)
add_ln(const float* __restrict__ A, const float* __restrict__ R,
       const float* __restrict__ bias,   // optional per-column bias (len D) or null
       const float* __restrict__ gam, const float* __restrict__ bet,
       float* __restrict__ Y)
{
    const int row = blockIdx.x;
    const float* a = A + (size_t)row * D;
    const float* r = R + (size_t)row * D;
    float*       y = Y + (size_t)row * D;

    __shared__ float xs[D];
    __shared__ float red[8];
    const int t = threadIdx.x;

    float lsum = 0.f;
    for (int i = t; i < D; i += 256) {
        float v = a[i] + r[i];
        if (bias) v += bias[i];
        xs[i] = v;
        lsum += v;
    }
    const float mu = block_sum_256(lsum, red) * (1.f / D);

    float lvar = 0.f;
    for (int i = t; i < D; i += 256) {
        const float d = xs[i] - mu;
        lvar += d * d;
    }
    const float var = block_sum_256(lvar, red) * (1.f / D);
    const float sdev = rsqrtf(var + 1e-5f);

    for (int i = t; i < D; i += 256)
        y[i] = (xs[i] - mu) * sdev * gam[i] + bet[i];
}

// ---------------------------------------------------------------------------
// Launch
// ---------------------------------------------------------------------------
extern "C" void kernel_launch(void* const* d_in, const int* in_sizes, int n_in,
                              void* d_out, int out_size)
{
    (void)in_sizes; (void)n_in; (void)out_size;

    const float* encoded = (const float*)d_in[0];
    const float* Yin     = (const float*)d_in[1];
    const unsigned char* maskb = (const unsigned char*)d_in[2];
    const unsigned char* padb  = (const unsigned char*)d_in[3];
    const float* Wq1 = (const float*)d_in[4];
    const float* Wk1 = (const float*)d_in[5];
    const float* Wv1 = (const float*)d_in[6];
    const float* ga1 = (const float*)d_in[7];
    const float* bb1 = (const float*)d_in[8];
    const float* Wq2 = (const float*)d_in[9];
    const float* Wk2 = (const float*)d_in[10];
    const float* Wv2 = (const float*)d_in[11];
    const float* ga2 = (const float*)d_in[12];
    const float* bb2 = (const float*)d_in[13];
    const float* We  = (const float*)d_in[14];
    const float* be  = (const float*)d_in[15];
    const float* Wc  = (const float*)d_in[16];
    const float* bc  = (const float*)d_in[17];
    const float* ga3 = (const float*)d_in[18];
    const float* bb3 = (const float*)d_in[19];
    float* out = (float*)d_out;

    float *pq, *pk, *pv, *pa, *py1, *py2, *ph, *ps;
    __nv_bfloat16 *pahi, *palo, *pbhi, *pblo;
    cudaGetSymbolAddress((void**)&pq,  g_q);
    cudaGetSymbolAddress((void**)&pk,  g_k);
    cudaGetSymbolAddress((void**)&pv,  g_v);
    cudaGetSymbolAddress((void**)&pa,  g_attn);
    cudaGetSymbolAddress((void**)&py1, g_y1);
    cudaGetSymbolAddress((void**)&py2, g_y2);
    cudaGetSymbolAddress((void**)&ph,  g_h);
    cudaGetSymbolAddress((void**)&ps,  g_s);
    cudaGetSymbolAddress((void**)&pahi, g_ahi);
    cudaGetSymbolAddress((void**)&palo, g_alo);
    cudaGetSymbolAddress((void**)&pbhi, g_bhi);
    cudaGetSymbolAddress((void**)&pblo, g_blo);

    cudaFuncSetAttribute(wmma_gemm, cudaFuncAttributeMaxDynamicSharedMemorySize,
                         GEMM_SMEM_BYTES);
    cudaFuncSetAttribute(wmma_gemm_b3, cudaFuncAttributeMaxDynamicSharedMemorySize,
                         GEMM_SMEM_BYTES);

    pad_prep_kernel<<<1, 256>>>(maskb, padb);

    const dim3 gScore(L / 64, L / 64, NHB);        // (16, 16, 64)
    const dim3 gOut(L / 64, NHB);                  // (16, 64)
    const dim3 gP3(D / 128, MROWS / 128, 3);       // batched projections: 768 CTAs
    const dim3 gF1(DFF / 128, MROWS / 128);        // FFN1: (32, 32)
    const dim3 gF2(D / 128, MROWS / 128);          // FFN2: (8, 32)

    constexpr int DDW  = D * D;          // one weight matrix (elems)
    constexpr int AOFF = MROWS * D;      // second activation slot (elems)

    auto conv = [&](const float* x, __nv_bfloat16* hi, __nv_bfloat16* lo, int n) {
        f32_to_bf16hl<<<(n / 4 + 255) / 256, 256>>>(x, hi, lo, n / 4);
    };

    // ---- masked self-attention + residual + LN ----
    conv(Yin, pahi, palo, MROWS * D);
    conv(Wq1, pbhi,           pblo,           DDW);
    conv(Wk1, pbhi + DDW,     pblo + DDW,     DDW);
    conv(Wv1, pbhi + 2 * DDW, pblo + 2 * DDW, DDW);
    {
        GemmBatch3 b;
        b.Ah[0] = b.Ah[1] = b.Ah[2] = pahi;
        b.Al[0] = b.Al[1] = b.Al[2] = palo;
        b.Bh[0] = pbhi;           b.Bl[0] = pblo;
        b.Bh[1] = pbhi + DDW;     b.Bl[1] = pblo + DDW;
        b.Bh[2] = pbhi + 2 * DDW; b.Bl[2] = pblo + 2 * DDW;
        b.C[0] = pq; b.C[1] = pk; b.C[2] = pv;
        wmma_gemm_b3<<<gP3, 256, GEMM_SMEM_BYTES>>>(b, MROWS, D, D);
    }
    attn_score<true><<<gScore, 256>>>(pq, pk, ps);
    softmax_rows<<<NHB * L, 128>>>(ps);
    attn_out<<<gOut, 256>>>(ps, pv, pa);
    add_ln<<<MROWS, 256>>>(pa, Yin, nullptr, ga1, bb1, py1);

    // ---- cross-attention + residual + LN ----
    conv(py1,     pahi,        palo,        MROWS * D);
    conv(encoded, pahi + AOFF, palo + AOFF, MROWS * D);
    conv(Wq2, pbhi,           pblo,           DDW);
    conv(Wk2, pbhi + DDW,     pblo + DDW,     DDW);
    conv(Wv2, pbhi + 2 * DDW, pblo + 2 * DDW, DDW);
    {
        GemmBatch3 b;
        b.Ah[0] = pahi;        b.Al[0] = palo;          // Q from py1
        b.Ah[1] = pahi + AOFF; b.Al[1] = palo + AOFF;   // K from encoded
        b.Ah[2] = pahi + AOFF; b.Al[2] = palo + AOFF;   // V from encoded
        b.Bh[0] = pbhi;           b.Bl[0] = pblo;
        b.Bh[1] = pbhi + DDW;     b.Bl[1] = pblo + DDW;
        b.Bh[2] = pbhi + 2 * DDW; b.Bl[2] = pblo + 2 * DDW;
        b.C[0] = pq; b.C[1] = pk; b.C[2] = pv;
        wmma_gemm_b3<<<gP3, 256, GEMM_SMEM_BYTES>>>(b, MROWS, D, D);
    }
    attn_score<false><<<gScore, 256>>>(pq, pk, ps);
    softmax_rows<<<NHB * L, 128>>>(ps);
    attn_out<<<gOut, 256>>>(ps, pv, pa);
    add_ln<<<MROWS, 256>>>(pa, py1, nullptr, ga2, bb2, py2);

    // ---- FFN + residual + LN ----
    conv(py2, pahi, palo, MROWS * D);
    conv(We, pbhi, pblo, DFF * D);
    wmma_gemm<<<gF1, 256, GEMM_SMEM_BYTES>>>(pahi, palo, pbhi, pblo, ph, MROWS, DFF, D);
    // bias + ReLU fused into the split-conversion of FFN1's output
    f32_to_bf16hl_br<<<(MROWS * DFF / 4 + 255) / 256, 256>>>(ph, be, pahi, palo,
                                                             MROWS * DFF / 4, DFF / 4);
    conv(Wc, pbhi, pblo, D * DFF);
    wmma_gemm<<<gF2, 256, GEMM_SMEM_BYTES>>>(pahi, palo, pbhi, pblo, pa, MROWS, D, DFF);
    // FFN2 bias fused into final add+LN
    add_ln<<<MROWS, 256>>>(pa, py2, bc, ga3, bb3, out);
}